// round 5
// baseline (speedup 1.0000x reference)
#include <cuda_runtime.h>

#define NLOC 1024
#define NNEI 64
#define NDIM 128
#define EDIM 64
#define ADIM 64
#define ASEL 20

typedef unsigned long long ull;

// ---------------- scratch (static device memory; no allocation) ----------------
__device__ float g_pself[NLOC * NDIM];        // silu(node @ W_self + b_self)
__device__ float g_pW0[NLOC * NDIM];          // node @ W0 + b_ne
__device__ float g_pW1[NLOC * NDIM];          // node @ W1
__device__ float g_pV0[NLOC * EDIM];          // node @ V0 + b_es
__device__ float g_pV1[NLOC * EDIM];          // node @ V1
__device__ float g_pA1[NLOC * EDIM];          // node @ A1 + b_ea1
__device__ float g_pB1[NLOC * ADIM];          // node @ B1 + b_as
__device__ float g_eproj[NLOC * ASEL * 4 * 64]; // [l][j][A2,A3,B2,B3][64]
__device__ float g_red[NLOC * ASEL * EDIM];   // reduced angle message
__device__ float g_symin[NLOC * 768];         // grrg concat input to W_sym
__device__ float g_nedge[NLOC * NDIM];        // n_edge

// ---------------- helpers ----------------
__device__ __forceinline__ float silu_f(float x) { return x / (1.0f + __expf(-x)); }

__device__ __forceinline__ ull pack2(float lo, float hi) {
    return (ull)__float_as_uint(lo) | ((ull)__float_as_uint(hi) << 32);
}
__device__ __forceinline__ float sum2(ull v) {
    return __uint_as_float((unsigned)v) + __uint_as_float((unsigned)(v >> 32));
}
__device__ __forceinline__ void fma2(ull &acc, ull a, ull b) {
    asm("fma.rn.f32x2 %0, %1, %2, %0;" : "+l"(acc) : "l"(a), "l"(b));
}

// ---------------- kernel A: per-node projections (16 nodes / block) ----------------
__global__ void k_nodeproj(const float* __restrict__ node,
                           const float* __restrict__ W_self, const float* __restrict__ b_self,
                           const float* __restrict__ W_ne,   const float* __restrict__ b_ne,
                           const float* __restrict__ W_es,   const float* __restrict__ b_es,
                           const float* __restrict__ W_ea1,  const float* __restrict__ b_ea1,
                           const float* __restrict__ W_as,   const float* __restrict__ b_as)
{
    const int t  = threadIdx.x;      // 0..127
    const int l0 = blockIdx.x * 16;
    __shared__ float xs[16][NDIM];
    for (int i = t; i < 16 * NDIM; i += 128) xs[i >> 7][i & 127] = node[l0 * NDIM + i];
    __syncthreads();

    // --- W_self ---
    {
        float acc[16];
        #pragma unroll
        for (int m = 0; m < 16; m++) acc[m] = 0.f;
        for (int k = 0; k < NDIM; k++) {
            float w = W_self[k * NDIM + t];
            #pragma unroll
            for (int m = 0; m < 16; m++) acc[m] = fmaf(xs[m][k], w, acc[m]);
        }
        float b = b_self[t];
        #pragma unroll
        for (int m = 0; m < 16; m++) g_pself[(l0 + m) * NDIM + t] = silu_f(acc[m] + b);
    }
    // --- W0 (node part of pre_ne), fold b_ne ---
    {
        float acc[16];
        #pragma unroll
        for (int m = 0; m < 16; m++) acc[m] = 0.f;
        for (int k = 0; k < NDIM; k++) {
            float w = W_ne[k * NDIM + t];
            #pragma unroll
            for (int m = 0; m < 16; m++) acc[m] = fmaf(xs[m][k], w, acc[m]);
        }
        float b = b_ne[t];
        #pragma unroll
        for (int m = 0; m < 16; m++) g_pW0[(l0 + m) * NDIM + t] = acc[m] + b;
    }
    // --- W1 (neighbor part of pre_ne) ---
    {
        float acc[16];
        #pragma unroll
        for (int m = 0; m < 16; m++) acc[m] = 0.f;
        for (int k = 0; k < NDIM; k++) {
            float w = W_ne[(NDIM + k) * NDIM + t];
            #pragma unroll
            for (int m = 0; m < 16; m++) acc[m] = fmaf(xs[m][k], w, acc[m]);
        }
        #pragma unroll
        for (int m = 0; m < 16; m++) g_pW1[(l0 + m) * NDIM + t] = acc[m];
    }
    // --- V0 / V1 (64-wide; t<64 -> V0, t>=64 -> V1) ---
    {
        const int d = t & 63;
        const float* Wp = W_es + ((t < 64) ? 0 : NDIM * EDIM) + d;
        float acc[16];
        #pragma unroll
        for (int m = 0; m < 16; m++) acc[m] = 0.f;
        for (int k = 0; k < NDIM; k++) {
            float w = Wp[k * EDIM];
            #pragma unroll
            for (int m = 0; m < 16; m++) acc[m] = fmaf(xs[m][k], w, acc[m]);
        }
        if (t < 64) {
            float b = b_es[d];
            #pragma unroll
            for (int m = 0; m < 16; m++) g_pV0[(l0 + m) * EDIM + d] = acc[m] + b;
        } else {
            #pragma unroll
            for (int m = 0; m < 16; m++) g_pV1[(l0 + m) * EDIM + d] = acc[m];
        }
    }
    // --- A1 / B1 (rows 64..191 of W_ea1 / W_as), fold biases ---
    {
        const int d = t & 63;
        const float* Wp = ((t < 64) ? W_ea1 : W_as) + 64 * 64 + d;
        float acc[16];
        #pragma unroll
        for (int m = 0; m < 16; m++) acc[m] = 0.f;
        for (int k = 0; k < NDIM; k++) {
            float w = Wp[k * 64];
            #pragma unroll
            for (int m = 0; m < 16; m++) acc[m] = fmaf(xs[m][k], w, acc[m]);
        }
        if (t < 64) {
            float b = b_ea1[d];
            #pragma unroll
            for (int m = 0; m < 16; m++) g_pA1[(l0 + m) * EDIM + d] = acc[m] + b;
        } else {
            float b = b_as[d];
            #pragma unroll
            for (int m = 0; m < 16; m++) g_pB1[(l0 + m) * ADIM + d] = acc[m] + b;
        }
    }
}

// ---------------- kernel A2: e_ang projections (A2,A3,B2,B3); 4 nodes / block ----------------
__global__ void k_eproj(const float* __restrict__ edge,
                        const float* __restrict__ W_ea1, const float* __restrict__ W_as)
{
    const int t  = threadIdx.x;      // 0..255
    const int l0 = blockIdx.x * 4;
    const int which = t >> 6;        // 0:A2 1:A3 2:B2 3:B3
    const int d = t & 63;
    const float* Wsrc = ((which < 2) ? W_ea1 : W_as) + ((which & 1) ? 256 * 64 : 192 * 64) + d;
    float w[64];
    #pragma unroll
    for (int k = 0; k < 64; k++) w[k] = Wsrc[k * 64];

    __shared__ float es[EDIM];
    for (int li = 0; li < 4; li++) {
        const int l = l0 + li;
        for (int jj = 0; jj < ASEL; jj++) {
            __syncthreads();
            if (t < 64) es[t] = edge[(l * NNEI + jj) * EDIM + t];
            __syncthreads();
            float acc = 0.f;
            #pragma unroll
            for (int k = 0; k < 64; k++) acc = fmaf(es[k], w[k], acc);
            g_eproj[((l * ASEL + jj) * 4 + which) * 64 + d] = acc;
        }
    }
}

// ---------------- kernel B: edge path + grrg + n_edge (block per node l) ----------------
__global__ void __launch_bounds__(192) k_edge(const float* __restrict__ node_ext,
                                              const float* __restrict__ edge,
                                              const float* __restrict__ h2,
                                              const float* __restrict__ sw,
                                              const int*   __restrict__ nlist,
                                              const float* __restrict__ W_ne,
                                              const float* __restrict__ W_es,
                                              const float* __restrict__ res_e,
                                              float* __restrict__ out_edge)
{
    const int t = threadIdx.x;   // 0..191
    const int l = blockIdx.x;
    __shared__ __align__(16) float e_sm[NNEI][EDIM];  // 16 KB
    __shared__ float sw_sm[NNEI];
    __shared__ int   nl_sm[NNEI];
    __shared__ float h2_sm[NNEI][3];
    __shared__ float hg_sm[3 * NDIM + 3 * EDIM];

    {
        const float4* src = (const float4*)(edge + l * NNEI * EDIM);
        float4* dst = (float4*)(&e_sm[0][0]);
        for (int i = t; i < NNEI * EDIM / 4; i += 192) dst[i] = src[i];
        for (int i = t; i < NNEI; i += 192) { sw_sm[i] = sw[l * NNEI + i]; nl_sm[i] = nlist[l * NNEI + i]; }
        for (int i = t; i < NNEI * 3; i += 192) h2_sm[i / 3][i % 3] = h2[l * NNEI * 3 + i];
    }
    __syncthreads();

    const bool isA = (t < NDIM);
    const int  d   = t - NDIM;   // only meaningful for !isA
    ull w2[32];
    if (isA) {
        #pragma unroll
        for (int kk = 0; kk < 32; kk++)
            w2[kk] = pack2(W_ne[(256 + 2 * kk) * NDIM + t], W_ne[(256 + 2 * kk + 1) * NDIM + t]);
    } else {
        #pragma unroll
        for (int kk = 0; kk < 32; kk++)
            w2[kk] = pack2(W_es[(256 + 2 * kk) * EDIM + d], W_es[(256 + 2 * kk + 1) * EDIM + d]);
    }
    const float pv0 = isA ? g_pW0[l * NDIM + t] : g_pV0[l * EDIM + d];
    const float rese0 = isA ? 0.f : res_e[d];

    float accNE = 0.f, hg0 = 0.f, hg1 = 0.f, hg2 = 0.f;

    for (int n = 0; n < NNEI; n++) {
        const int   idx = nl_sm[n];
        const float swv = sw_sm[n];
        const ull* ep = (const ull*)(&e_sm[n][0]);
        ull a0 = 0, a1 = 0;
        #pragma unroll
        for (int kk = 0; kk < 32; kk += 2) { fma2(a0, w2[kk], ep[kk]); fma2(a1, w2[kk + 1], ep[kk + 1]); }
        float s = sum2(a0) + sum2(a1) + pv0;
        if (isA) {
            s += g_pW1[idx * NDIM + t];
            accNE = fmaf(silu_f(s), swv, accNE);
            float gw = node_ext[idx * NDIM + t] * swv;
            hg0 = fmaf(h2_sm[n][0], gw, hg0);
            hg1 = fmaf(h2_sm[n][1], gw, hg1);
            hg2 = fmaf(h2_sm[n][2], gw, hg2);
        } else {
            s += g_pV1[idx * EDIM + d];
            float es = silu_f(s);
            float ev = e_sm[n][d];
            out_edge[(l * NNEI + n) * EDIM + d] = fmaf(rese0, es, ev);
            float ge = ev * swv;
            hg0 = fmaf(h2_sm[n][0], ge, hg0);
            hg1 = fmaf(h2_sm[n][1], ge, hg1);
            hg2 = fmaf(h2_sm[n][2], ge, hg2);
        }
    }
    const float inv_nnei = 1.0f / NNEI;
    if (isA) {
        g_nedge[l * NDIM + t] = accNE * inv_nnei;
        hg_sm[0 * NDIM + t] = hg0 * inv_nnei;
        hg_sm[1 * NDIM + t] = hg1 * inv_nnei;
        hg_sm[2 * NDIM + t] = hg2 * inv_nnei;
    } else {
        hg_sm[3 * NDIM + 0 * EDIM + d] = hg0 * inv_nnei;
        hg_sm[3 * NDIM + 1 * EDIM + d] = hg1 * inv_nnei;
        hg_sm[3 * NDIM + 2 * EDIM + d] = hg2 * inv_nnei;
    }
    __syncthreads();

    // grrg outer products -> g_symin[l][768]   ([grrg(edge) 256 | grrg(nei) 512])
    const float third = 1.0f / 3.0f;
    #pragma unroll
    for (int g = 0; g < 4; g++) {
        int v = t + g * 192;
        float o;
        if (v < 256) {
            int a = v >> 6, dd = v & 63;
            const float* he = hg_sm + 3 * NDIM;
            o = (he[0 * EDIM + a] * he[0 * EDIM + dd] +
                 he[1 * EDIM + a] * he[1 * EDIM + dd] +
                 he[2 * EDIM + a] * he[2 * EDIM + dd]) * third;
        } else {
            int vv = v - 256;
            int a = vv >> 7, c = vv & 127;
            o = (hg_sm[0 * NDIM + a] * hg_sm[0 * NDIM + c] +
                 hg_sm[1 * NDIM + a] * hg_sm[1 * NDIM + c] +
                 hg_sm[2 * NDIM + a] * hg_sm[2 * NDIM + c]) * third;
        }
        g_symin[l * 768 + v] = o;
    }
}

// ---------------- kernel E: node_sym GEMM + node finalize (4 nodes / block) ----------------
__global__ void k_node_fin(const float* __restrict__ node,
                           const float* __restrict__ W_sym, const float* __restrict__ b_sym,
                           const float* __restrict__ res_n, float* __restrict__ out_node)
{
    const int t  = threadIdx.x;     // 0..127
    const int l0 = blockIdx.x * 4;
    __shared__ float xs[4][768];
    for (int i = t; i < 4 * 768; i += 128) xs[i / 768][i % 768] = g_symin[l0 * 768 + i];
    __syncthreads();

    float acc[4] = {0.f, 0.f, 0.f, 0.f};
    for (int k = 0; k < 768; k++) {
        float w = W_sym[k * NDIM + t];
        #pragma unroll
        for (int m = 0; m < 4; m++) acc[m] = fmaf(xs[m][k], w, acc[m]);
    }
    const float b  = b_sym[t];
    const float r0 = res_n[t], r1 = res_n[NDIM + t], r2 = res_n[2 * NDIM + t];
    #pragma unroll
    for (int m = 0; m < 4; m++) {
        const int l = l0 + m;
        float ns = silu_f(acc[m] + b);
        out_node[l * NDIM + t] = node[l * NDIM + t]
                               + r0 * g_pself[l * NDIM + t]
                               + r1 * ns
                               + r2 * g_nedge[l * NDIM + t];
    }
}

// ---------------- kernel C: fused angle path (block per node l, loops i,j) ----------------
__global__ void __launch_bounds__(128) k_angle(const float* __restrict__ angle,
                                               const float* __restrict__ a_sw,
                                               const float* __restrict__ W_ea1,
                                               const float* __restrict__ W_as,
                                               const float* __restrict__ res_a,
                                               float* __restrict__ out_angle)
{
    const int t = threadIdx.x;     // 0..127
    const int l = blockIdx.x;
    const bool isA = (t < 64);     // A path: e_ang_upd -> reduced ; B path: angle_self -> angle_new
    const int  d   = t & 63;

    ull w2[32];
    {
        const float* Wsrc = isA ? W_ea1 : W_as;   // A0 / B0 live in rows 0..63
        #pragma unroll
        for (int kk = 0; kk < 32; kk++)
            w2[kk] = pack2(Wsrc[(2 * kk) * 64 + d], Wsrc[(2 * kk + 1) * 64 + d]);
    }

    __shared__ __align__(16) float rows[ASEL][64];   // angle rows for current i
    __shared__ float asw_sm[ASEL];
    if (t < ASEL) asw_sm[t] = a_sw[l * ASEL + t];

    const float* eproj_l = g_eproj + l * ASEL * 256;
    const float baseconst = isA ? g_pA1[l * 64 + d] : g_pB1[l * 64 + d];
    const float resv = res_a[d];
    const float inv_sqrt_asel = 0.22360679774997896f;  // 1/sqrt(20)

    for (int i = 0; i < ASEL; i++) {
        __syncthreads();
        {
            const float4* src = (const float4*)(angle + (size_t)((l * ASEL + i) * ASEL) * 64);
            float4* dst = (float4*)(&rows[0][0]);
            for (int q = t; q < ASEL * 64 / 4; q += 128) dst[q] = src[q];
        }
        __syncthreads();

        const float base = baseconst + (isA ? eproj_l[i * 256 + 64 + d]      // A3[e_ang[l,i]]
                                            : eproj_l[i * 256 + 192 + d]);   // B3[e_ang[l,i]]
        float red = 0.f;
        for (int j = 0; j < ASEL; j++) {
            const ull* xp = (const ull*)(&rows[j][0]);
            ull a0 = 0, a1 = 0;
            #pragma unroll
            for (int kk = 0; kk < 32; kk += 2) { fma2(a0, w2[kk], xp[kk]); fma2(a1, w2[kk + 1], xp[kk + 1]); }
            const float add = isA ? eproj_l[j * 256 + 0 + d]                 // A2[e_ang[l,j]]
                                  : eproj_l[j * 256 + 128 + d];              // B2[e_ang[l,j]]
            const float v = silu_f(sum2(a0) + sum2(a1) + base + add);
            if (isA) {
                red = fmaf(asw_sm[j], v, red);
            } else {
                size_t o = (size_t)((l * ASEL + i) * ASEL + j) * 64 + d;
                out_angle[o] = fmaf(resv, v, rows[j][d]);
            }
        }
        if (isA)
            g_red[(l * ASEL + i) * 64 + d] = red * asw_sm[i] * inv_sqrt_asel;
    }
}

// ---------------- kernel D: e_angle_msg GEMM + edge finalize ----------------
__global__ void __launch_bounds__(64) k_eamsg(const float* __restrict__ W_ea2,
                                              const float* __restrict__ b_ea2,
                                              const float* __restrict__ res_e,
                                              float* __restrict__ out_edge)
{
    const int d = threadIdx.x;   // 0..63
    const int l = blockIdx.x;
    ull w2[32];
    #pragma unroll
    for (int kk = 0; kk < 32; kk++)
        w2[kk] = pack2(W_ea2[(2 * kk) * 64 + d], W_ea2[(2 * kk + 1) * 64 + d]);
    const float b   = b_ea2[d];
    const float re1 = res_e[64 + d];

    __shared__ __align__(16) float xs[ASEL][64];
    for (int q = d; q < ASEL * 64; q += 64) ((float*)xs)[q] = g_red[l * ASEL * 64 + q];
    __syncthreads();

    const float ypad = re1 * silu_f(b);   // padded rows contribute silu(b)
    for (int i = 0; i < NNEI; i++) {
        float add;
        if (i < ASEL) {
            const ull* xp = (const ull*)(&xs[i][0]);
            ull a0 = 0, a1 = 0;
            #pragma unroll
            for (int kk = 0; kk < 32; kk += 2) { fma2(a0, w2[kk], xp[kk]); fma2(a1, w2[kk + 1], xp[kk + 1]); }
            add = re1 * silu_f(sum2(a0) + sum2(a1) + b);
        } else {
            add = ypad;
        }
        const size_t o = (size_t)(l * NNEI + i) * 64 + d;
        out_edge[o] += add;
    }
}

// ---------------- launch ----------------
extern "C" void kernel_launch(void* const* d_in, const int* in_sizes, int n_in,
                              void* d_out, int out_size)
{
    (void)in_sizes; (void)n_in; (void)out_size;
    const float* node_ext = (const float*)d_in[0];
    const float* edge     = (const float*)d_in[1];
    const float* h2       = (const float*)d_in[2];
    const float* angle    = (const float*)d_in[3];
    const float* sw       = (const float*)d_in[4];
    const float* a_sw     = (const float*)d_in[5];
    const float* W_self   = (const float*)d_in[6];
    const float* b_self   = (const float*)d_in[7];
    const float* W_sym    = (const float*)d_in[8];
    const float* b_sym    = (const float*)d_in[9];
    const float* W_ne     = (const float*)d_in[10];
    const float* b_ne     = (const float*)d_in[11];
    const float* W_es     = (const float*)d_in[12];
    const float* b_es     = (const float*)d_in[13];
    const float* W_ea1    = (const float*)d_in[14];
    const float* b_ea1    = (const float*)d_in[15];
    const float* W_ea2    = (const float*)d_in[16];
    const float* b_ea2    = (const float*)d_in[17];
    const float* W_as     = (const float*)d_in[18];
    const float* b_as     = (const float*)d_in[19];
    const float* res_n    = (const float*)d_in[20];
    const float* res_e    = (const float*)d_in[21];
    const float* res_a    = (const float*)d_in[22];
    const int*   nlist    = (const int*)d_in[23];
    // d_in[24], d_in[25]: nlist_mask / a_nlist_mask — all True in this problem's setup

    float* out_node  = (float*)d_out;
    float* out_edge  = out_node + NLOC * NDIM;
    float* out_angle = out_edge + NLOC * NNEI * EDIM;

    k_nodeproj<<<NLOC / 16, 128>>>(node_ext, W_self, b_self, W_ne, b_ne,
                                   W_es, b_es, W_ea1, b_ea1, W_as, b_as);
    k_eproj<<<NLOC / 4, 256>>>(edge, W_ea1, W_as);
    k_edge<<<NLOC, 192>>>(node_ext, edge, h2, sw, nlist, W_ne, W_es, res_e, out_edge);
    k_node_fin<<<NLOC / 4, 128>>>(node_ext, W_sym, b_sym, res_n, out_node);
    k_angle<<<NLOC, 128>>>(angle, a_sw, W_ea1, W_as, res_a, out_angle);
    k_eamsg<<<NLOC, 64>>>(W_ea2, b_ea2, res_e, out_edge);
}

// round 6
// speedup vs baseline: 1.3147x; 1.3147x over previous
#include <cuda_runtime.h>

#define NLOC 1024
#define NNEI 64
#define NDIM 128
#define EDIM 64
#define ADIM 64
#define ASEL 20

typedef unsigned long long ull;

// ---------------- scratch (static device memory; no allocation) ----------------
__device__ float g_pself[NLOC * NDIM];        // silu(node @ W_self + b_self)
__device__ float g_pW0[NLOC * NDIM];          // node @ W0 + b_ne
__device__ float g_pW1[NLOC * NDIM];          // node @ W1
__device__ float g_pV0[NLOC * EDIM];          // node @ V0 + b_es
__device__ float g_pV1[NLOC * EDIM];          // node @ V1
__device__ float g_pA1[NLOC * EDIM];          // node @ A1 + b_ea1
__device__ float g_pB1[NLOC * ADIM];          // node @ B1 + b_as
__device__ float g_eproj[NLOC * ASEL * 4 * 64]; // [l][j][A2,A3,B2,B3][64]
__device__ float g_red[NLOC * ASEL * EDIM];   // reduced angle message
__device__ float g_symin[NLOC * 768];         // grrg concat input to W_sym
__device__ float g_nedge[NLOC * NDIM];        // n_edge

// ---------------- helpers ----------------
__device__ __forceinline__ float silu_f(float x) { return x / (1.0f + __expf(-x)); }

__device__ __forceinline__ ull pack2(float lo, float hi) {
    ull r;
    asm("mov.b64 %0, {%1, %2};" : "=l"(r) : "f"(lo), "f"(hi));
    return r;
}
__device__ __forceinline__ float sum2(ull v) {
    float lo, hi;
    asm("mov.b64 {%0, %1}, %2;" : "=f"(lo), "=f"(hi) : "l"(v));
    return lo + hi;
}
__device__ __forceinline__ void fma2(ull &acc, ull a, ull b) {
    asm("fma.rn.f32x2 %0, %1, %2, %0;" : "+l"(acc) : "l"(a), "l"(b));
}
__device__ __forceinline__ ull lo2(float4 v) { return pack2(v.x, v.y); }
__device__ __forceinline__ ull hi2(float4 v) { return pack2(v.z, v.w); }

// ---------------- kernel A: per-node projections (16 nodes / block, pass = blockIdx.y) ----------------
__global__ void __launch_bounds__(128) k_nodeproj(
        const float* __restrict__ node,
        const float* __restrict__ W_self, const float* __restrict__ b_self,
        const float* __restrict__ W_ne,   const float* __restrict__ b_ne,
        const float* __restrict__ W_es,   const float* __restrict__ b_es,
        const float* __restrict__ W_ea1,  const float* __restrict__ b_ea1,
        const float* __restrict__ W_as,   const float* __restrict__ b_as)
{
    const int t    = threadIdx.x;      // 0..127
    const int l0   = blockIdx.x * 16;
    const int pass = blockIdx.y;       // 0:W_self 1:W0 2:W1 3:V0/V1 4:A1/B1
    __shared__ __align__(16) float xs[16][NDIM];
    {
        const float4* src = (const float4*)(node + l0 * NDIM);
        float4* dst = (float4*)(&xs[0][0]);
        #pragma unroll
        for (int i = 0; i < 4; i++) dst[t + 128 * i] = src[t + 128 * i];
    }
    __syncthreads();

    float acc[16];
    #pragma unroll
    for (int m = 0; m < 16; m++) acc[m] = 0.f;

    if (pass < 3) {
        const float* W = (pass == 0) ? W_self : ((pass == 1) ? W_ne : (W_ne + NDIM * NDIM));
        for (int k = 0; k < NDIM; k += 4) {
            float w0 = W[(k + 0) * NDIM + t];
            float w1 = W[(k + 1) * NDIM + t];
            float w2 = W[(k + 2) * NDIM + t];
            float w3 = W[(k + 3) * NDIM + t];
            #pragma unroll
            for (int m = 0; m < 16; m++) {
                float4 x = *(const float4*)(&xs[m][k]);
                acc[m] = fmaf(x.x, w0, acc[m]);
                acc[m] = fmaf(x.y, w1, acc[m]);
                acc[m] = fmaf(x.z, w2, acc[m]);
                acc[m] = fmaf(x.w, w3, acc[m]);
            }
        }
        if (pass == 0) {
            float b = b_self[t];
            #pragma unroll
            for (int m = 0; m < 16; m++) g_pself[(l0 + m) * NDIM + t] = silu_f(acc[m] + b);
        } else if (pass == 1) {
            float b = b_ne[t];
            #pragma unroll
            for (int m = 0; m < 16; m++) g_pW0[(l0 + m) * NDIM + t] = acc[m] + b;
        } else {
            #pragma unroll
            for (int m = 0; m < 16; m++) g_pW1[(l0 + m) * NDIM + t] = acc[m];
        }
    } else {
        const int d = t & 63;
        const float* W;
        if (pass == 3) W = W_es + ((t < 64) ? 0 : NDIM * EDIM) + d;
        else           W = ((t < 64) ? W_ea1 : W_as) + 64 * 64 + d;
        for (int k = 0; k < NDIM; k += 4) {
            float w0 = W[(k + 0) * 64];
            float w1 = W[(k + 1) * 64];
            float w2 = W[(k + 2) * 64];
            float w3 = W[(k + 3) * 64];
            #pragma unroll
            for (int m = 0; m < 16; m++) {
                float4 x = *(const float4*)(&xs[m][k]);
                acc[m] = fmaf(x.x, w0, acc[m]);
                acc[m] = fmaf(x.y, w1, acc[m]);
                acc[m] = fmaf(x.z, w2, acc[m]);
                acc[m] = fmaf(x.w, w3, acc[m]);
            }
        }
        if (pass == 3) {
            if (t < 64) {
                float b = b_es[d];
                #pragma unroll
                for (int m = 0; m < 16; m++) g_pV0[(l0 + m) * EDIM + d] = acc[m] + b;
            } else {
                #pragma unroll
                for (int m = 0; m < 16; m++) g_pV1[(l0 + m) * EDIM + d] = acc[m];
            }
        } else {
            if (t < 64) {
                float b = b_ea1[d];
                #pragma unroll
                for (int m = 0; m < 16; m++) g_pA1[(l0 + m) * EDIM + d] = acc[m] + b;
            } else {
                float b = b_as[d];
                #pragma unroll
                for (int m = 0; m < 16; m++) g_pB1[(l0 + m) * ADIM + d] = acc[m] + b;
            }
        }
    }
}

// ---------------- kernel A2: e_ang projections (A2,A3,B2,B3); 2 nodes / block ----------------
__global__ void __launch_bounds__(256) k_eproj(const float* __restrict__ edge,
                                               const float* __restrict__ W_ea1,
                                               const float* __restrict__ W_as)
{
    const int t  = threadIdx.x;      // 0..255
    const int l0 = blockIdx.x * 2;
    const int which = t >> 6;        // 0:A2 1:A3 2:B2 3:B3
    const int d = t & 63;
    const float* Wsrc = ((which < 2) ? W_ea1 : W_as) + ((which & 1) ? 256 * 64 : 192 * 64) + d;
    ull w2[32];
    #pragma unroll
    for (int kk = 0; kk < 32; kk++)
        w2[kk] = pack2(Wsrc[(2 * kk) * 64], Wsrc[(2 * kk + 1) * 64]);

    __shared__ __align__(16) float rows[ASEL][64];   // 5 KB

    for (int li = 0; li < 2; li++) {
        const int l = l0 + li;
        __syncthreads();
        {
            const float4* src = (const float4*)(edge + (size_t)l * NNEI * EDIM);
            float4* dst = (float4*)(&rows[0][0]);
            for (int q = t; q < ASEL * 16; q += 256) dst[q] = src[q];
        }
        __syncthreads();
        for (int j = 0; j < ASEL; j++) {
            const float4* xp = (const float4*)(&rows[j][0]);
            ull a0 = 0, a1 = 0;
            #pragma unroll
            for (int kk = 0; kk < 16; kk++) {
                float4 v = xp[kk];
                fma2(a0, w2[2 * kk],     lo2(v));
                fma2(a1, w2[2 * kk + 1], hi2(v));
            }
            g_eproj[((l * ASEL + j) * 4 + which) * 64 + d] = sum2(a0) + sum2(a1);
        }
    }
}

// ---------------- kernel B: edge path + grrg + n_edge (block per node l) ----------------
__global__ void __launch_bounds__(192) k_edge(const float* __restrict__ node_ext,
                                              const float* __restrict__ edge,
                                              const float* __restrict__ h2,
                                              const float* __restrict__ sw,
                                              const int*   __restrict__ nlist,
                                              const float* __restrict__ W_ne,
                                              const float* __restrict__ W_es,
                                              const float* __restrict__ res_e,
                                              float* __restrict__ out_edge)
{
    const int t = threadIdx.x;   // 0..191
    const int l = blockIdx.x;
    __shared__ __align__(16) float e_sm[NNEI][EDIM];  // 16 KB
    __shared__ float sw_sm[NNEI];
    __shared__ int   nl_sm[NNEI];
    __shared__ float h2_sm[NNEI][3];
    __shared__ float hg_sm[3 * NDIM + 3 * EDIM];

    {
        const float4* src = (const float4*)(edge + (size_t)l * NNEI * EDIM);
        float4* dst = (float4*)(&e_sm[0][0]);
        for (int i = t; i < NNEI * EDIM / 4; i += 192) dst[i] = src[i];
        for (int i = t; i < NNEI; i += 192) { sw_sm[i] = sw[l * NNEI + i]; nl_sm[i] = nlist[l * NNEI + i]; }
        for (int i = t; i < NNEI * 3; i += 192) h2_sm[i / 3][i % 3] = h2[l * NNEI * 3 + i];
    }
    __syncthreads();

    const bool isA = (t < NDIM);
    const int  d   = t - NDIM;   // only meaningful for !isA
    ull w2[32];
    if (isA) {
        #pragma unroll
        for (int kk = 0; kk < 32; kk++)
            w2[kk] = pack2(W_ne[(256 + 2 * kk) * NDIM + t], W_ne[(256 + 2 * kk + 1) * NDIM + t]);
    } else {
        #pragma unroll
        for (int kk = 0; kk < 32; kk++)
            w2[kk] = pack2(W_es[(256 + 2 * kk) * EDIM + d], W_es[(256 + 2 * kk + 1) * EDIM + d]);
    }
    const float pv0 = isA ? g_pW0[l * NDIM + t] : g_pV0[l * EDIM + d];
    const float rese0 = isA ? 0.f : res_e[d];

    float accNE = 0.f, hg0 = 0.f, hg1 = 0.f, hg2 = 0.f;

    for (int n = 0; n < NNEI; n += 2) {
        const int   idx0 = nl_sm[n],     idx1 = nl_sm[n + 1];
        const float sw0  = sw_sm[n],     sw1  = sw_sm[n + 1];
        const float4* xp0 = (const float4*)(&e_sm[n][0]);
        const float4* xp1 = (const float4*)(&e_sm[n + 1][0]);
        ull a0 = 0, a1 = 0, c0 = 0, c1 = 0;
        #pragma unroll
        for (int kk = 0; kk < 16; kk++) {
            float4 v0 = xp0[kk];
            float4 v1 = xp1[kk];
            fma2(a0, w2[2 * kk],     lo2(v0));
            fma2(a1, w2[2 * kk + 1], hi2(v0));
            fma2(c0, w2[2 * kk],     lo2(v1));
            fma2(c1, w2[2 * kk + 1], hi2(v1));
        }
        float s0 = sum2(a0) + sum2(a1) + pv0;
        float s1 = sum2(c0) + sum2(c1) + pv0;
        if (isA) {
            s0 += g_pW1[idx0 * NDIM + t];
            s1 += g_pW1[idx1 * NDIM + t];
            accNE = fmaf(silu_f(s0), sw0, accNE);
            accNE = fmaf(silu_f(s1), sw1, accNE);
            float gw0 = node_ext[idx0 * NDIM + t] * sw0;
            float gw1 = node_ext[idx1 * NDIM + t] * sw1;
            hg0 = fmaf(h2_sm[n][0], gw0, fmaf(h2_sm[n + 1][0], gw1, hg0));
            hg1 = fmaf(h2_sm[n][1], gw0, fmaf(h2_sm[n + 1][1], gw1, hg1));
            hg2 = fmaf(h2_sm[n][2], gw0, fmaf(h2_sm[n + 1][2], gw1, hg2));
        } else {
            s0 += g_pV1[idx0 * EDIM + d];
            s1 += g_pV1[idx1 * EDIM + d];
            float ev0 = e_sm[n][d], ev1 = e_sm[n + 1][d];
            out_edge[(l * NNEI + n)     * EDIM + d] = fmaf(rese0, silu_f(s0), ev0);
            out_edge[(l * NNEI + n + 1) * EDIM + d] = fmaf(rese0, silu_f(s1), ev1);
            float ge0 = ev0 * sw0, ge1 = ev1 * sw1;
            hg0 = fmaf(h2_sm[n][0], ge0, fmaf(h2_sm[n + 1][0], ge1, hg0));
            hg1 = fmaf(h2_sm[n][1], ge0, fmaf(h2_sm[n + 1][1], ge1, hg1));
            hg2 = fmaf(h2_sm[n][2], ge0, fmaf(h2_sm[n + 1][2], ge1, hg2));
        }
    }
    const float inv_nnei = 1.0f / NNEI;
    if (isA) {
        g_nedge[l * NDIM + t] = accNE * inv_nnei;
        hg_sm[0 * NDIM + t] = hg0 * inv_nnei;
        hg_sm[1 * NDIM + t] = hg1 * inv_nnei;
        hg_sm[2 * NDIM + t] = hg2 * inv_nnei;
    } else {
        hg_sm[3 * NDIM + 0 * EDIM + d] = hg0 * inv_nnei;
        hg_sm[3 * NDIM + 1 * EDIM + d] = hg1 * inv_nnei;
        hg_sm[3 * NDIM + 2 * EDIM + d] = hg2 * inv_nnei;
    }
    __syncthreads();

    // grrg outer products -> g_symin[l][768]   ([grrg(edge) 256 | grrg(nei) 512])
    const float third = 1.0f / 3.0f;
    #pragma unroll
    for (int g = 0; g < 4; g++) {
        int v = t + g * 192;
        float o;
        if (v < 256) {
            int a = v >> 6, dd = v & 63;
            const float* he = hg_sm + 3 * NDIM;
            o = (he[0 * EDIM + a] * he[0 * EDIM + dd] +
                 he[1 * EDIM + a] * he[1 * EDIM + dd] +
                 he[2 * EDIM + a] * he[2 * EDIM + dd]) * third;
        } else {
            int vv = v - 256;
            int a = vv >> 7, c = vv & 127;
            o = (hg_sm[0 * NDIM + a] * hg_sm[0 * NDIM + c] +
                 hg_sm[1 * NDIM + a] * hg_sm[1 * NDIM + c] +
                 hg_sm[2 * NDIM + a] * hg_sm[2 * NDIM + c]) * third;
        }
        g_symin[l * 768 + v] = o;
    }
}

// ---------------- kernel E: node_sym GEMM + node finalize (8 nodes / block, k split 2) ----------------
__global__ void __launch_bounds__(256) k_node_fin(const float* __restrict__ node,
                                                  const float* __restrict__ W_sym,
                                                  const float* __restrict__ b_sym,
                                                  const float* __restrict__ res_n,
                                                  float* __restrict__ out_node)
{
    const int t    = threadIdx.x;     // 0..255
    const int tt   = t & 127;
    const int half = t >> 7;
    const int l0   = blockIdx.x * 8;
    __shared__ __align__(16) float xs[8][768];   // 24 KB
    __shared__ float part[8][NDIM];              // 4 KB
    {
        const float4* src = (const float4*)(g_symin + (size_t)l0 * 768);
        float4* dst = (float4*)(&xs[0][0]);
        #pragma unroll
        for (int i = 0; i < 6; i++) dst[t + 256 * i] = src[t + 256 * i];
    }
    __syncthreads();

    float acc[8];
    #pragma unroll
    for (int m = 0; m < 8; m++) acc[m] = 0.f;
    const int k0 = half * 384;
    for (int k = k0; k < k0 + 384; k += 4) {
        float w0 = W_sym[(k + 0) * NDIM + tt];
        float w1 = W_sym[(k + 1) * NDIM + tt];
        float w2 = W_sym[(k + 2) * NDIM + tt];
        float w3 = W_sym[(k + 3) * NDIM + tt];
        #pragma unroll
        for (int m = 0; m < 8; m++) {
            float4 x = *(const float4*)(&xs[m][k]);
            acc[m] = fmaf(x.x, w0, acc[m]);
            acc[m] = fmaf(x.y, w1, acc[m]);
            acc[m] = fmaf(x.z, w2, acc[m]);
            acc[m] = fmaf(x.w, w3, acc[m]);
        }
    }
    if (half == 1) {
        #pragma unroll
        for (int m = 0; m < 8; m++) part[m][tt] = acc[m];
    }
    __syncthreads();
    if (half == 0) {
        const float b  = b_sym[tt];
        const float r0 = res_n[tt], r1 = res_n[NDIM + tt], r2 = res_n[2 * NDIM + tt];
        #pragma unroll
        for (int m = 0; m < 8; m++) {
            const int l = l0 + m;
            float ns = silu_f(acc[m] + part[m][tt] + b);
            out_node[l * NDIM + tt] = node[l * NDIM + tt]
                                    + r0 * g_pself[l * NDIM + tt]
                                    + r1 * ns
                                    + r2 * g_nedge[l * NDIM + tt];
        }
    }
}

// ---------------- kernel C: fused angle path (block per node l, loops i,j) ----------------
__global__ void __launch_bounds__(128) k_angle(const float* __restrict__ angle,
                                               const float* __restrict__ a_sw,
                                               const float* __restrict__ W_ea1,
                                               const float* __restrict__ W_as,
                                               const float* __restrict__ res_a,
                                               float* __restrict__ out_angle)
{
    const int t = threadIdx.x;     // 0..127
    const int l = blockIdx.x;
    const bool isA = (t < 64);     // A path: e_ang_upd -> reduced ; B path: angle_self -> angle_new
    const int  d   = t & 63;

    ull w2[32];
    {
        const float* Wsrc = isA ? W_ea1 : W_as;   // A0 / B0 live in rows 0..63
        #pragma unroll
        for (int kk = 0; kk < 32; kk++)
            w2[kk] = pack2(Wsrc[(2 * kk) * 64 + d], Wsrc[(2 * kk + 1) * 64 + d]);
    }

    __shared__ __align__(16) float rows[ASEL][64];   // angle rows for current i
    __shared__ float asw_sm[ASEL];
    if (t < ASEL) asw_sm[t] = a_sw[l * ASEL + t];

    const float* eproj_l = g_eproj + (size_t)l * ASEL * 256;
    const float baseconst = isA ? g_pA1[l * 64 + d] : g_pB1[l * 64 + d];
    const float resv = res_a[d];
    const float inv_sqrt_asel = 0.22360679774997896f;  // 1/sqrt(20)

    for (int i = 0; i < ASEL; i++) {
        __syncthreads();
        {
            const float4* src = (const float4*)(angle + (size_t)((l * ASEL + i) * ASEL) * 64);
            float4* dst = (float4*)(&rows[0][0]);
            #pragma unroll
            for (int q = 0; q < 3; q++) {
                int idx = t + 128 * q;
                if (idx < ASEL * 16) dst[idx] = src[idx];
            }
        }
        __syncthreads();

        const float base = baseconst + (isA ? eproj_l[i * 256 + 64 + d]      // A3[e_ang[l,i]]
                                            : eproj_l[i * 256 + 192 + d]);   // B3[e_ang[l,i]]
        float red = 0.f;
        for (int j = 0; j < ASEL; j++) {
            const float4* xp = (const float4*)(&rows[j][0]);
            ull a0 = 0, a1 = 0;
            #pragma unroll
            for (int kk = 0; kk < 16; kk++) {
                float4 v = xp[kk];
                fma2(a0, w2[2 * kk],     lo2(v));
                fma2(a1, w2[2 * kk + 1], hi2(v));
            }
            const float add = isA ? eproj_l[j * 256 + 0 + d]                 // A2[e_ang[l,j]]
                                  : eproj_l[j * 256 + 128 + d];              // B2[e_ang[l,j]]
            const float v = silu_f(sum2(a0) + sum2(a1) + base + add);
            if (isA) {
                red = fmaf(asw_sm[j], v, red);
            } else {
                size_t o = (size_t)((l * ASEL + i) * ASEL + j) * 64 + d;
                out_angle[o] = fmaf(resv, v, rows[j][d]);
            }
        }
        if (isA)
            g_red[(l * ASEL + i) * 64 + d] = red * asw_sm[i] * inv_sqrt_asel;
    }
}

// ---------------- kernel D: e_angle_msg GEMM + edge finalize (2 nodes / block) ----------------
__global__ void __launch_bounds__(128) k_eamsg(const float* __restrict__ W_ea2,
                                               const float* __restrict__ b_ea2,
                                               const float* __restrict__ res_e,
                                               float* __restrict__ out_edge)
{
    const int t = threadIdx.x;   // 0..127
    const int d = t & 63;
    const int l = blockIdx.x * 2 + (t >> 6);
    ull w2[32];
    #pragma unroll
    for (int kk = 0; kk < 32; kk++)
        w2[kk] = pack2(W_ea2[(2 * kk) * 64 + d], W_ea2[(2 * kk + 1) * 64 + d]);
    const float b   = b_ea2[d];
    const float re1 = res_e[64 + d];

    __shared__ __align__(16) float xs[2][ASEL][64];   // 10 KB
    {
        const float4* src = (const float4*)(g_red + (size_t)(blockIdx.x * 2) * ASEL * 64);
        float4* dst = (float4*)(&xs[0][0][0]);
        for (int q = t; q < 2 * ASEL * 16; q += 128) dst[q] = src[q];
    }
    __syncthreads();

    const float ypad = re1 * silu_f(b);   // padded rows contribute silu(b)
    for (int i = 0; i < NNEI; i++) {
        float add;
        if (i < ASEL) {
            const float4* xp = (const float4*)(&xs[t >> 6][i][0]);
            ull a0 = 0, a1 = 0;
            #pragma unroll
            for (int kk = 0; kk < 16; kk++) {
                float4 v = xp[kk];
                fma2(a0, w2[2 * kk],     lo2(v));
                fma2(a1, w2[2 * kk + 1], hi2(v));
            }
            add = re1 * silu_f(sum2(a0) + sum2(a1) + b);
        } else {
            add = ypad;
        }
        const size_t o = (size_t)(l * NNEI + i) * 64 + d;
        out_edge[o] += add;
    }
}

// ---------------- launch ----------------
extern "C" void kernel_launch(void* const* d_in, const int* in_sizes, int n_in,
                              void* d_out, int out_size)
{
    (void)in_sizes; (void)n_in; (void)out_size;
    const float* node_ext = (const float*)d_in[0];
    const float* edge     = (const float*)d_in[1];
    const float* h2       = (const float*)d_in[2];
    const float* angle    = (const float*)d_in[3];
    const float* sw       = (const float*)d_in[4];
    const float* a_sw     = (const float*)d_in[5];
    const float* W_self   = (const float*)d_in[6];
    const float* b_self   = (const float*)d_in[7];
    const float* W_sym    = (const float*)d_in[8];
    const float* b_sym    = (const float*)d_in[9];
    const float* W_ne     = (const float*)d_in[10];
    const float* b_ne     = (const float*)d_in[11];
    const float* W_es     = (const float*)d_in[12];
    const float* b_es     = (const float*)d_in[13];
    const float* W_ea1    = (const float*)d_in[14];
    const float* b_ea1    = (const float*)d_in[15];
    const float* W_ea2    = (const float*)d_in[16];
    const float* b_ea2    = (const float*)d_in[17];
    const float* W_as     = (const float*)d_in[18];
    const float* b_as     = (const float*)d_in[19];
    const float* res_n    = (const float*)d_in[20];
    const float* res_e    = (const float*)d_in[21];
    const float* res_a    = (const float*)d_in[22];
    const int*   nlist    = (const int*)d_in[23];
    // d_in[24], d_in[25]: nlist_mask / a_nlist_mask — all True in this problem's setup

    float* out_node  = (float*)d_out;
    float* out_edge  = out_node + NLOC * NDIM;
    float* out_angle = out_edge + NLOC * NNEI * EDIM;

    k_nodeproj<<<dim3(NLOC / 16, 5), 128>>>(node_ext, W_self, b_self, W_ne, b_ne,
                                            W_es, b_es, W_ea1, b_ea1, W_as, b_as);
    k_eproj<<<NLOC / 2, 256>>>(edge, W_ea1, W_as);
    k_edge<<<NLOC, 192>>>(node_ext, edge, h2, sw, nlist, W_ne, W_es, res_e, out_edge);
    k_node_fin<<<NLOC / 8, 256>>>(node_ext, W_sym, b_sym, res_n, out_node);
    k_angle<<<NLOC, 128>>>(angle, a_sw, W_ea1, W_as, res_a, out_angle);
    k_eamsg<<<NLOC / 2, 128>>>(W_ea2, b_ea2, res_e, out_edge);
}

// round 7
// speedup vs baseline: 1.7719x; 1.3478x over previous
#include <cuda_runtime.h>

#define NLOC 1024
#define NNEI 64
#define NDIM 128
#define EDIM 64
#define ADIM 64
#define ASEL 20

typedef unsigned long long ull;

// ---------------- scratch (static device memory; no allocation) ----------------
__device__ float g_pself[NLOC * NDIM];        // silu(node @ W_self + b_self)
__device__ float g_pW0[NLOC * NDIM];          // node @ W0 + b_ne
__device__ float g_pW1[NLOC * NDIM];          // node @ W1
__device__ float g_pV0[NLOC * EDIM];          // node @ V0 + b_es
__device__ float g_pV1[NLOC * EDIM];          // node @ V1
__device__ float g_pA1[NLOC * EDIM];          // node @ A1 + b_ea1
__device__ float g_pB1[NLOC * ADIM];          // node @ B1 + b_as
__device__ float g_eproj[NLOC * ASEL * 4 * 64]; // [l][j][A2,A3,B2,B3][64]
__device__ float g_red[NLOC * ASEL * EDIM];   // reduced angle message
__device__ float g_symin[NLOC * 768];         // grrg concat input to W_sym
__device__ float g_nedge[NLOC * NDIM];        // n_edge

// ---------------- helpers ----------------
__device__ __forceinline__ float silu_f(float x) { return x / (1.0f + __expf(-x)); }

__device__ __forceinline__ ull pack2(float lo, float hi) {
    ull r;
    asm("mov.b64 %0, {%1, %2};" : "=l"(r) : "f"(lo), "f"(hi));
    return r;
}
__device__ __forceinline__ float sum2(ull v) {
    float lo, hi;
    asm("mov.b64 {%0, %1}, %2;" : "=f"(lo), "=f"(hi) : "l"(v));
    return lo + hi;
}
__device__ __forceinline__ void fma2(ull &acc, ull a, ull b) {
    asm("fma.rn.f32x2 %0, %1, %2, %0;" : "+l"(acc) : "l"(a), "l"(b));
}
__device__ __forceinline__ ull lo2(float4 v) { return pack2(v.x, v.y); }
__device__ __forceinline__ ull hi2(float4 v) { return pack2(v.z, v.w); }

// ---------------- kernel A: per-node projections (16 nodes / block, pass = blockIdx.y) ----------------
__global__ void __launch_bounds__(128) k_nodeproj(
        const float* __restrict__ node,
        const float* __restrict__ W_self, const float* __restrict__ b_self,
        const float* __restrict__ W_ne,   const float* __restrict__ b_ne,
        const float* __restrict__ W_es,   const float* __restrict__ b_es,
        const float* __restrict__ W_ea1,  const float* __restrict__ b_ea1,
        const float* __restrict__ W_as,   const float* __restrict__ b_as)
{
    const int t    = threadIdx.x;      // 0..127
    const int l0   = blockIdx.x * 16;
    const int pass = blockIdx.y;       // 0:W_self 1:W0 2:W1 3:V0/V1 4:A1/B1
    __shared__ __align__(16) float xs[16][NDIM];
    {
        const float4* src = (const float4*)(node + l0 * NDIM);
        float4* dst = (float4*)(&xs[0][0]);
        #pragma unroll
        for (int i = 0; i < 4; i++) dst[t + 128 * i] = src[t + 128 * i];
    }
    __syncthreads();

    float acc[16];
    #pragma unroll
    for (int m = 0; m < 16; m++) acc[m] = 0.f;

    if (pass < 3) {
        const float* W = (pass == 0) ? W_self : ((pass == 1) ? W_ne : (W_ne + NDIM * NDIM));
        for (int k = 0; k < NDIM; k += 4) {
            float w0 = W[(k + 0) * NDIM + t];
            float w1 = W[(k + 1) * NDIM + t];
            float w2 = W[(k + 2) * NDIM + t];
            float w3 = W[(k + 3) * NDIM + t];
            #pragma unroll
            for (int m = 0; m < 16; m++) {
                float4 x = *(const float4*)(&xs[m][k]);
                acc[m] = fmaf(x.x, w0, acc[m]);
                acc[m] = fmaf(x.y, w1, acc[m]);
                acc[m] = fmaf(x.z, w2, acc[m]);
                acc[m] = fmaf(x.w, w3, acc[m]);
            }
        }
        if (pass == 0) {
            float b = b_self[t];
            #pragma unroll
            for (int m = 0; m < 16; m++) g_pself[(l0 + m) * NDIM + t] = silu_f(acc[m] + b);
        } else if (pass == 1) {
            float b = b_ne[t];
            #pragma unroll
            for (int m = 0; m < 16; m++) g_pW0[(l0 + m) * NDIM + t] = acc[m] + b;
        } else {
            #pragma unroll
            for (int m = 0; m < 16; m++) g_pW1[(l0 + m) * NDIM + t] = acc[m];
        }
    } else {
        const int d = t & 63;
        const float* W;
        if (pass == 3) W = W_es + ((t < 64) ? 0 : NDIM * EDIM) + d;
        else           W = ((t < 64) ? W_ea1 : W_as) + 64 * 64 + d;
        for (int k = 0; k < NDIM; k += 4) {
            float w0 = W[(k + 0) * 64];
            float w1 = W[(k + 1) * 64];
            float w2 = W[(k + 2) * 64];
            float w3 = W[(k + 3) * 64];
            #pragma unroll
            for (int m = 0; m < 16; m++) {
                float4 x = *(const float4*)(&xs[m][k]);
                acc[m] = fmaf(x.x, w0, acc[m]);
                acc[m] = fmaf(x.y, w1, acc[m]);
                acc[m] = fmaf(x.z, w2, acc[m]);
                acc[m] = fmaf(x.w, w3, acc[m]);
            }
        }
        if (pass == 3) {
            if (t < 64) {
                float b = b_es[d];
                #pragma unroll
                for (int m = 0; m < 16; m++) g_pV0[(l0 + m) * EDIM + d] = acc[m] + b;
            } else {
                #pragma unroll
                for (int m = 0; m < 16; m++) g_pV1[(l0 + m) * EDIM + d] = acc[m];
            }
        } else {
            if (t < 64) {
                float b = b_ea1[d];
                #pragma unroll
                for (int m = 0; m < 16; m++) g_pA1[(l0 + m) * EDIM + d] = acc[m] + b;
            } else {
                float b = b_as[d];
                #pragma unroll
                for (int m = 0; m < 16; m++) g_pB1[(l0 + m) * ADIM + d] = acc[m] + b;
            }
        }
    }
}

// ---------------- kernel A2: e_ang projections (A2,A3,B2,B3); 2 nodes / block ----------------
__global__ void __launch_bounds__(256) k_eproj(const float* __restrict__ edge,
                                               const float* __restrict__ W_ea1,
                                               const float* __restrict__ W_as)
{
    const int t  = threadIdx.x;      // 0..255
    const int l0 = blockIdx.x * 2;
    const int which = t >> 6;        // 0:A2 1:A3 2:B2 3:B3
    const int d = t & 63;
    const float* Wsrc = ((which < 2) ? W_ea1 : W_as) + ((which & 1) ? 256 * 64 : 192 * 64) + d;
    ull w2[32];
    #pragma unroll
    for (int kk = 0; kk < 32; kk++)
        w2[kk] = pack2(Wsrc[(2 * kk) * 64], Wsrc[(2 * kk + 1) * 64]);

    __shared__ __align__(16) float rows[ASEL][64];   // 5 KB

    for (int li = 0; li < 2; li++) {
        const int l = l0 + li;
        __syncthreads();
        {
            const float4* src = (const float4*)(edge + (size_t)l * NNEI * EDIM);
            float4* dst = (float4*)(&rows[0][0]);
            for (int q = t; q < ASEL * 16; q += 256) dst[q] = src[q];
        }
        __syncthreads();
        for (int j = 0; j < ASEL; j += 2) {
            const float4* xp0 = (const float4*)(&rows[j][0]);
            const float4* xp1 = (const float4*)(&rows[j + 1][0]);
            ull a0 = 0, a1 = 0, c0 = 0, c1 = 0;
            #pragma unroll
            for (int kk = 0; kk < 16; kk++) {
                float4 v0 = xp0[kk];
                float4 v1 = xp1[kk];
                fma2(a0, w2[2 * kk],     lo2(v0));
                fma2(a1, w2[2 * kk + 1], hi2(v0));
                fma2(c0, w2[2 * kk],     lo2(v1));
                fma2(c1, w2[2 * kk + 1], hi2(v1));
            }
            g_eproj[((l * ASEL + j)     * 4 + which) * 64 + d] = sum2(a0) + sum2(a1);
            g_eproj[((l * ASEL + j + 1) * 4 + which) * 64 + d] = sum2(c0) + sum2(c1);
        }
    }
}

// ---------------- kernel B: edge path + grrg + n_edge (block per node l) ----------------
__global__ void __launch_bounds__(192) k_edge(const float* __restrict__ node_ext,
                                              const float* __restrict__ edge,
                                              const float* __restrict__ h2,
                                              const float* __restrict__ sw,
                                              const int*   __restrict__ nlist,
                                              const float* __restrict__ W_ne,
                                              const float* __restrict__ W_es,
                                              const float* __restrict__ res_e,
                                              float* __restrict__ out_edge)
{
    const int t = threadIdx.x;   // 0..191
    const int l = blockIdx.x;
    __shared__ __align__(16) float e_sm[NNEI][EDIM];  // 16 KB
    __shared__ float sw_sm[NNEI];
    __shared__ int   nl_sm[NNEI];
    __shared__ float h2_sm[NNEI][3];
    __shared__ float hg_sm[3 * NDIM + 3 * EDIM];

    {
        const float4* src = (const float4*)(edge + (size_t)l * NNEI * EDIM);
        float4* dst = (float4*)(&e_sm[0][0]);
        for (int i = t; i < NNEI * EDIM / 4; i += 192) dst[i] = src[i];
        for (int i = t; i < NNEI; i += 192) { sw_sm[i] = sw[l * NNEI + i]; nl_sm[i] = nlist[l * NNEI + i]; }
        for (int i = t; i < NNEI * 3; i += 192) h2_sm[i / 3][i % 3] = h2[l * NNEI * 3 + i];
    }
    __syncthreads();

    const bool isA = (t < NDIM);
    const int  d   = t - NDIM;   // only meaningful for !isA
    ull w2[32];
    if (isA) {
        #pragma unroll
        for (int kk = 0; kk < 32; kk++)
            w2[kk] = pack2(W_ne[(256 + 2 * kk) * NDIM + t], W_ne[(256 + 2 * kk + 1) * NDIM + t]);
    } else {
        #pragma unroll
        for (int kk = 0; kk < 32; kk++)
            w2[kk] = pack2(W_es[(256 + 2 * kk) * EDIM + d], W_es[(256 + 2 * kk + 1) * EDIM + d]);
    }
    const float pv0 = isA ? g_pW0[l * NDIM + t] : g_pV0[l * EDIM + d];
    const float rese0 = isA ? 0.f : res_e[d];

    float accNE = 0.f, hg0 = 0.f, hg1 = 0.f, hg2 = 0.f;

    for (int n = 0; n < NNEI; n += 2) {
        const int   idx0 = nl_sm[n],     idx1 = nl_sm[n + 1];
        const float sw0  = sw_sm[n],     sw1  = sw_sm[n + 1];
        // hoist random gathers so they overlap the fma chains
        float gproj0, gproj1, gnode0 = 0.f, gnode1 = 0.f;
        if (isA) {
            gproj0 = g_pW1[idx0 * NDIM + t];
            gproj1 = g_pW1[idx1 * NDIM + t];
            gnode0 = node_ext[idx0 * NDIM + t];
            gnode1 = node_ext[idx1 * NDIM + t];
        } else {
            gproj0 = g_pV1[idx0 * EDIM + d];
            gproj1 = g_pV1[idx1 * EDIM + d];
        }
        const float4* xp0 = (const float4*)(&e_sm[n][0]);
        const float4* xp1 = (const float4*)(&e_sm[n + 1][0]);
        ull a0 = 0, a1 = 0, c0 = 0, c1 = 0;
        #pragma unroll
        for (int kk = 0; kk < 16; kk++) {
            float4 v0 = xp0[kk];
            float4 v1 = xp1[kk];
            fma2(a0, w2[2 * kk],     lo2(v0));
            fma2(a1, w2[2 * kk + 1], hi2(v0));
            fma2(c0, w2[2 * kk],     lo2(v1));
            fma2(c1, w2[2 * kk + 1], hi2(v1));
        }
        float s0 = sum2(a0) + sum2(a1) + pv0 + gproj0;
        float s1 = sum2(c0) + sum2(c1) + pv0 + gproj1;
        if (isA) {
            accNE = fmaf(silu_f(s0), sw0, accNE);
            accNE = fmaf(silu_f(s1), sw1, accNE);
            float gw0 = gnode0 * sw0;
            float gw1 = gnode1 * sw1;
            hg0 = fmaf(h2_sm[n][0], gw0, fmaf(h2_sm[n + 1][0], gw1, hg0));
            hg1 = fmaf(h2_sm[n][1], gw0, fmaf(h2_sm[n + 1][1], gw1, hg1));
            hg2 = fmaf(h2_sm[n][2], gw0, fmaf(h2_sm[n + 1][2], gw1, hg2));
        } else {
            float ev0 = e_sm[n][d], ev1 = e_sm[n + 1][d];
            out_edge[(l * NNEI + n)     * EDIM + d] = fmaf(rese0, silu_f(s0), ev0);
            out_edge[(l * NNEI + n + 1) * EDIM + d] = fmaf(rese0, silu_f(s1), ev1);
            float ge0 = ev0 * sw0, ge1 = ev1 * sw1;
            hg0 = fmaf(h2_sm[n][0], ge0, fmaf(h2_sm[n + 1][0], ge1, hg0));
            hg1 = fmaf(h2_sm[n][1], ge0, fmaf(h2_sm[n + 1][1], ge1, hg1));
            hg2 = fmaf(h2_sm[n][2], ge0, fmaf(h2_sm[n + 1][2], ge1, hg2));
        }
    }
    const float inv_nnei = 1.0f / NNEI;
    if (isA) {
        g_nedge[l * NDIM + t] = accNE * inv_nnei;
        hg_sm[0 * NDIM + t] = hg0 * inv_nnei;
        hg_sm[1 * NDIM + t] = hg1 * inv_nnei;
        hg_sm[2 * NDIM + t] = hg2 * inv_nnei;
    } else {
        hg_sm[3 * NDIM + 0 * EDIM + d] = hg0 * inv_nnei;
        hg_sm[3 * NDIM + 1 * EDIM + d] = hg1 * inv_nnei;
        hg_sm[3 * NDIM + 2 * EDIM + d] = hg2 * inv_nnei;
    }
    __syncthreads();

    // grrg outer products -> g_symin[l][768]   ([grrg(edge) 256 | grrg(nei) 512])
    const float third = 1.0f / 3.0f;
    #pragma unroll
    for (int g = 0; g < 4; g++) {
        int v = t + g * 192;
        float o;
        if (v < 256) {
            int a = v >> 6, dd = v & 63;
            const float* he = hg_sm + 3 * NDIM;
            o = (he[0 * EDIM + a] * he[0 * EDIM + dd] +
                 he[1 * EDIM + a] * he[1 * EDIM + dd] +
                 he[2 * EDIM + a] * he[2 * EDIM + dd]) * third;
        } else {
            int vv = v - 256;
            int a = vv >> 7, c = vv & 127;
            o = (hg_sm[0 * NDIM + a] * hg_sm[0 * NDIM + c] +
                 hg_sm[1 * NDIM + a] * hg_sm[1 * NDIM + c] +
                 hg_sm[2 * NDIM + a] * hg_sm[2 * NDIM + c]) * third;
        }
        g_symin[l * 768 + v] = o;
    }
}

// ---------------- kernel E: node_sym GEMM + finalize (4 nodes / block, split-k 4, 512 thr) ----------------
__global__ void __launch_bounds__(512) k_node_fin(const float* __restrict__ node,
                                                  const float* __restrict__ W_sym,
                                                  const float* __restrict__ b_sym,
                                                  const float* __restrict__ res_n,
                                                  float* __restrict__ out_node)
{
    const int t  = threadIdx.x;     // 0..511
    const int tt = t & 127;
    const int q  = t >> 7;          // k quarter 0..3
    const int l0 = blockIdx.x * 4;
    __shared__ __align__(16) float xs[4][768];   // 12 KB
    __shared__ float part[3][4][NDIM];           // 6 KB
    {
        const float4* src = (const float4*)(g_symin + (size_t)l0 * 768);
        float4* dst = (float4*)(&xs[0][0]);
        for (int i = t; i < 768; i += 512) dst[i] = src[i];
    }
    __syncthreads();

    float acc[4] = {0.f, 0.f, 0.f, 0.f};
    const int k0 = q * 192;
    #pragma unroll 2
    for (int k = k0; k < k0 + 192; k += 4) {
        float w0 = W_sym[(k + 0) * NDIM + tt];
        float w1 = W_sym[(k + 1) * NDIM + tt];
        float w2 = W_sym[(k + 2) * NDIM + tt];
        float w3 = W_sym[(k + 3) * NDIM + tt];
        #pragma unroll
        for (int m = 0; m < 4; m++) {
            float4 x = *(const float4*)(&xs[m][k]);
            acc[m] = fmaf(x.x, w0, acc[m]);
            acc[m] = fmaf(x.y, w1, acc[m]);
            acc[m] = fmaf(x.z, w2, acc[m]);
            acc[m] = fmaf(x.w, w3, acc[m]);
        }
    }
    if (q > 0) {
        #pragma unroll
        for (int m = 0; m < 4; m++) part[q - 1][m][tt] = acc[m];
    }
    __syncthreads();
    if (q == 0) {
        const float b  = b_sym[tt];
        const float r0 = res_n[tt], r1 = res_n[NDIM + tt], r2 = res_n[2 * NDIM + tt];
        #pragma unroll
        for (int m = 0; m < 4; m++) {
            const int l = l0 + m;
            float s = acc[m] + part[0][m][tt] + part[1][m][tt] + part[2][m][tt] + b;
            float ns = silu_f(s);
            out_node[l * NDIM + tt] = node[l * NDIM + tt]
                                    + r0 * g_pself[l * NDIM + tt]
                                    + r1 * ns
                                    + r2 * g_nedge[l * NDIM + tt];
        }
    }
}

// ---------------- kernel C: fused angle path (block per node l, loops i,j) ----------------
__global__ void __launch_bounds__(128) k_angle(const float* __restrict__ angle,
                                               const float* __restrict__ a_sw,
                                               const float* __restrict__ W_ea1,
                                               const float* __restrict__ W_as,
                                               const float* __restrict__ res_a,
                                               float* __restrict__ out_angle)
{
    const int t = threadIdx.x;     // 0..127
    const int l = blockIdx.x;
    const bool isA = (t < 64);     // A path: e_ang_upd -> reduced ; B path: angle_self -> angle_new
    const int  d   = t & 63;

    ull w2[32];
    {
        const float* Wsrc = isA ? W_ea1 : W_as;   // A0 / B0 live in rows 0..63
        #pragma unroll
        for (int kk = 0; kk < 32; kk++)
            w2[kk] = pack2(Wsrc[(2 * kk) * 64 + d], Wsrc[(2 * kk + 1) * 64 + d]);
    }

    __shared__ __align__(16) float rows[ASEL][64];   // angle rows for current i
    __shared__ float asw_sm[ASEL];
    if (t < ASEL) asw_sm[t] = a_sw[l * ASEL + t];

    const float* eproj_l = g_eproj + (size_t)l * ASEL * 256;

    // preload the per-j additive projections (A2 / B2) into registers
    float addj[ASEL];
    {
        const int off = isA ? 0 : 128;
        #pragma unroll
        for (int j = 0; j < ASEL; j++) addj[j] = eproj_l[j * 256 + off + d];
    }
    const float baseconst = isA ? g_pA1[l * 64 + d] : g_pB1[l * 64 + d];
    const float resv = res_a[d];
    const float inv_sqrt_asel = 0.22360679774997896f;  // 1/sqrt(20)
    const int base_off = isA ? 64 : 192;

    for (int i = 0; i < ASEL; i++) {
        __syncthreads();
        {
            const float4* src = (const float4*)(angle + (size_t)((l * ASEL + i) * ASEL) * 64);
            float4* dst = (float4*)(&rows[0][0]);
            #pragma unroll
            for (int q = 0; q < 3; q++) {
                int idx = t + 128 * q;
                if (idx < ASEL * 16) dst[idx] = src[idx];
            }
        }
        __syncthreads();

        const float base = baseconst + eproj_l[i * 256 + base_off + d];
        float red = 0.f;
        #pragma unroll 2
        for (int j = 0; j < ASEL; j += 2) {
            const float4* xp0 = (const float4*)(&rows[j][0]);
            const float4* xp1 = (const float4*)(&rows[j + 1][0]);
            ull a0 = 0, a1 = 0, c0 = 0, c1 = 0;
            #pragma unroll
            for (int kk = 0; kk < 16; kk++) {
                float4 v0 = xp0[kk];
                float4 v1 = xp1[kk];
                fma2(a0, w2[2 * kk],     lo2(v0));
                fma2(a1, w2[2 * kk + 1], hi2(v0));
                fma2(c0, w2[2 * kk],     lo2(v1));
                fma2(c1, w2[2 * kk + 1], hi2(v1));
            }
            const float v_0 = silu_f(sum2(a0) + sum2(a1) + base + addj[j]);
            const float v_1 = silu_f(sum2(c0) + sum2(c1) + base + addj[j + 1]);
            if (isA) {
                red = fmaf(asw_sm[j],     v_0, red);
                red = fmaf(asw_sm[j + 1], v_1, red);
            } else {
                size_t o = (size_t)((l * ASEL + i) * ASEL + j) * 64 + d;
                out_angle[o]      = fmaf(resv, v_0, rows[j][d]);
                out_angle[o + 64] = fmaf(resv, v_1, rows[j + 1][d]);
            }
        }
        if (isA)
            g_red[(l * ASEL + i) * 64 + d] = red * asw_sm[i] * inv_sqrt_asel;
    }
}

// ---------------- kernel D: e_angle_msg GEMM + edge finalize (2 nodes / block) ----------------
__global__ void __launch_bounds__(128) k_eamsg(const float* __restrict__ W_ea2,
                                               const float* __restrict__ b_ea2,
                                               const float* __restrict__ res_e,
                                               float* __restrict__ out_edge)
{
    const int t = threadIdx.x;   // 0..127
    const int d = t & 63;
    const int l = blockIdx.x * 2 + (t >> 6);
    ull w2[32];
    #pragma unroll
    for (int kk = 0; kk < 32; kk++)
        w2[kk] = pack2(W_ea2[(2 * kk) * 64 + d], W_ea2[(2 * kk + 1) * 64 + d]);
    const float b   = b_ea2[d];
    const float re1 = res_e[64 + d];

    __shared__ __align__(16) float xs[2][ASEL][64];   // 10 KB
    {
        const float4* src = (const float4*)(g_red + (size_t)(blockIdx.x * 2) * ASEL * 64);
        float4* dst = (float4*)(&xs[0][0][0]);
        for (int q = t; q < 2 * ASEL * 16; q += 128) dst[q] = src[q];
    }
    __syncthreads();

    const float ypad = re1 * silu_f(b);   // padded rows contribute silu(b)
    for (int i = 0; i < NNEI; i++) {
        float add;
        if (i < ASEL) {
            const float4* xp = (const float4*)(&xs[t >> 6][i][0]);
            ull a0 = 0, a1 = 0;
            #pragma unroll
            for (int kk = 0; kk < 16; kk++) {
                float4 v = xp[kk];
                fma2(a0, w2[2 * kk],     lo2(v));
                fma2(a1, w2[2 * kk + 1], hi2(v));
            }
            add = re1 * silu_f(sum2(a0) + sum2(a1) + b);
        } else {
            add = ypad;
        }
        const size_t o = (size_t)(l * NNEI + i) * 64 + d;
        out_edge[o] += add;
    }
}

// ---------------- stream/event resources (created once, at load time) ----------------
struct HxStreams {
    cudaStream_t s1 = nullptr;
    cudaEvent_t  evNP = nullptr, evEdge = nullptr, evJoin = nullptr;
    bool ok = false;
    HxStreams() {
        ok = (cudaStreamCreateWithFlags(&s1, cudaStreamNonBlocking) == cudaSuccess) &&
             (cudaEventCreateWithFlags(&evNP,   cudaEventDisableTiming) == cudaSuccess) &&
             (cudaEventCreateWithFlags(&evEdge, cudaEventDisableTiming) == cudaSuccess) &&
             (cudaEventCreateWithFlags(&evJoin, cudaEventDisableTiming) == cudaSuccess);
    }
};
static HxStreams g_hx;

// ---------------- launch ----------------
extern "C" void kernel_launch(void* const* d_in, const int* in_sizes, int n_in,
                              void* d_out, int out_size)
{
    (void)in_sizes; (void)n_in; (void)out_size;
    const float* node_ext = (const float*)d_in[0];
    const float* edge     = (const float*)d_in[1];
    const float* h2       = (const float*)d_in[2];
    const float* angle    = (const float*)d_in[3];
    const float* sw       = (const float*)d_in[4];
    const float* a_sw     = (const float*)d_in[5];
    const float* W_self   = (const float*)d_in[6];
    const float* b_self   = (const float*)d_in[7];
    const float* W_sym    = (const float*)d_in[8];
    const float* b_sym    = (const float*)d_in[9];
    const float* W_ne     = (const float*)d_in[10];
    const float* b_ne     = (const float*)d_in[11];
    const float* W_es     = (const float*)d_in[12];
    const float* b_es     = (const float*)d_in[13];
    const float* W_ea1    = (const float*)d_in[14];
    const float* b_ea1    = (const float*)d_in[15];
    const float* W_ea2    = (const float*)d_in[16];
    const float* b_ea2    = (const float*)d_in[17];
    const float* W_as     = (const float*)d_in[18];
    const float* b_as     = (const float*)d_in[19];
    const float* res_n    = (const float*)d_in[20];
    const float* res_e    = (const float*)d_in[21];
    const float* res_a    = (const float*)d_in[22];
    const int*   nlist    = (const int*)d_in[23];
    // d_in[24], d_in[25]: nlist_mask / a_nlist_mask — all True in this problem's setup

    float* out_node  = (float*)d_out;
    float* out_edge  = out_node + NLOC * NDIM;
    float* out_angle = out_edge + NLOC * NNEI * EDIM;

    if (g_hx.ok) {
        cudaStream_t s0 = 0, s1 = g_hx.s1;
        // chain 0: nodeproj -> edge -> node_fin
        k_nodeproj<<<dim3(NLOC / 16, 5), 128, 0, s0>>>(node_ext, W_self, b_self, W_ne, b_ne,
                                                       W_es, b_es, W_ea1, b_ea1, W_as, b_as);
        cudaEventRecord(g_hx.evNP, s0);
        // chain 1: eproj (independent), then angle after nodeproj
        k_eproj<<<NLOC / 2, 256, 0, s1>>>(edge, W_ea1, W_as);
        cudaStreamWaitEvent(s1, g_hx.evNP, 0);
        k_edge<<<NLOC, 192, 0, s0>>>(node_ext, edge, h2, sw, nlist, W_ne, W_es, res_e, out_edge);
        cudaEventRecord(g_hx.evEdge, s0);
        k_angle<<<NLOC, 128, 0, s1>>>(angle, a_sw, W_ea1, W_as, res_a, out_angle);
        k_node_fin<<<NLOC / 4, 512, 0, s0>>>(node_ext, W_sym, b_sym, res_n, out_node);
        cudaStreamWaitEvent(s1, g_hx.evEdge, 0);
        k_eamsg<<<NLOC / 2, 128, 0, s1>>>(W_ea2, b_ea2, res_e, out_edge);
        cudaEventRecord(g_hx.evJoin, s1);
        cudaStreamWaitEvent(s0, g_hx.evJoin, 0);
    } else {
        // serial fallback (correct, no overlap)
        k_nodeproj<<<dim3(NLOC / 16, 5), 128>>>(node_ext, W_self, b_self, W_ne, b_ne,
                                                W_es, b_es, W_ea1, b_ea1, W_as, b_as);
        k_eproj<<<NLOC / 2, 256>>>(edge, W_ea1, W_as);
        k_edge<<<NLOC, 192>>>(node_ext, edge, h2, sw, nlist, W_ne, W_es, res_e, out_edge);
        k_node_fin<<<NLOC / 4, 512>>>(node_ext, W_sym, b_sym, res_n, out_node);
        k_angle<<<NLOC, 128>>>(angle, a_sw, W_ea1, W_as, res_a, out_angle);
        k_eamsg<<<NLOC / 2, 128>>>(W_ea2, b_ea2, res_e, out_edge);
    }
}

// round 8
// speedup vs baseline: 2.0138x; 1.1365x over previous
#include <cuda_runtime.h>

#define NLOC 1024
#define NNEI 64
#define NDIM 128
#define EDIM 64
#define ADIM 64
#define ASEL 20

typedef unsigned long long ull;

// ---------------- scratch (static device memory; no allocation) ----------------
__device__ float g_pself[NLOC * NDIM];        // silu(node @ W_self + b_self)
__device__ float g_pW0[NLOC * NDIM];          // node @ W0 + b_ne
__device__ float g_pW1[NLOC * NDIM];          // node @ W1
__device__ float g_pV0[NLOC * EDIM];          // node @ V0 + b_es
__device__ float g_pV1[NLOC * EDIM];          // node @ V1
__device__ float g_pA1[NLOC * EDIM];          // node @ A1 + b_ea1
__device__ float g_pB1[NLOC * ADIM];          // node @ B1 + b_as
__device__ float g_eproj[NLOC * ASEL * 4 * 64]; // [l][j][A2,A3,B2,B3][64]
__device__ float g_red[NLOC * ASEL * EDIM];   // reduced angle message
__device__ float g_symin[NLOC * 768];         // grrg concat input to W_sym
__device__ float g_nedge[NLOC * NDIM];        // n_edge

// ---------------- helpers ----------------
__device__ __forceinline__ float silu_f(float x) { return x / (1.0f + __expf(-x)); }

__device__ __forceinline__ ull pack2(float lo, float hi) {
    ull r;
    asm("mov.b64 %0, {%1, %2};" : "=l"(r) : "f"(lo), "f"(hi));
    return r;
}
__device__ __forceinline__ float sum2(ull v) {
    float lo, hi;
    asm("mov.b64 {%0, %1}, %2;" : "=f"(lo), "=f"(hi) : "l"(v));
    return lo + hi;
}
__device__ __forceinline__ void fma2(ull &acc, ull a, ull b) {
    asm("fma.rn.f32x2 %0, %1, %2, %0;" : "+l"(acc) : "l"(a), "l"(b));
}
// 128-bit shared load directly into two 64-bit register pairs (no repacking movs)
__device__ __forceinline__ void lds_2x64(ull &a, ull &b, unsigned saddr) {
    asm volatile("ld.shared.v2.u64 {%0, %1}, [%2];" : "=l"(a), "=l"(b) : "r"(saddr));
}
__device__ __forceinline__ unsigned saddr_of(const void* p) {
    return (unsigned)__cvta_generic_to_shared(p);
}

// ---------------- kernel A: per-node projections (16 nodes / block, pass = blockIdx.y) ----------------
__global__ void __launch_bounds__(128) k_nodeproj(
        const float* __restrict__ node,
        const float* __restrict__ W_self, const float* __restrict__ b_self,
        const float* __restrict__ W_ne,   const float* __restrict__ b_ne,
        const float* __restrict__ W_es,   const float* __restrict__ b_es,
        const float* __restrict__ W_ea1,  const float* __restrict__ b_ea1,
        const float* __restrict__ W_as,   const float* __restrict__ b_as)
{
    const int t    = threadIdx.x;      // 0..127
    const int l0   = blockIdx.x * 16;
    const int pass = blockIdx.y;       // 0:W_self 1:W0 2:W1 3:V0/V1 4:A1/B1
    __shared__ __align__(16) float xs[16][NDIM];
    {
        const float4* src = (const float4*)(node + l0 * NDIM);
        float4* dst = (float4*)(&xs[0][0]);
        #pragma unroll
        for (int i = 0; i < 4; i++) dst[t + 128 * i] = src[t + 128 * i];
    }
    __syncthreads();

    float acc[16];
    #pragma unroll
    for (int m = 0; m < 16; m++) acc[m] = 0.f;

    if (pass < 3) {
        const float* W = (pass == 0) ? W_self : ((pass == 1) ? W_ne : (W_ne + NDIM * NDIM));
        for (int k = 0; k < NDIM; k += 4) {
            float w0 = W[(k + 0) * NDIM + t];
            float w1 = W[(k + 1) * NDIM + t];
            float w2 = W[(k + 2) * NDIM + t];
            float w3 = W[(k + 3) * NDIM + t];
            #pragma unroll
            for (int m = 0; m < 16; m++) {
                float4 x = *(const float4*)(&xs[m][k]);
                acc[m] = fmaf(x.x, w0, acc[m]);
                acc[m] = fmaf(x.y, w1, acc[m]);
                acc[m] = fmaf(x.z, w2, acc[m]);
                acc[m] = fmaf(x.w, w3, acc[m]);
            }
        }
        if (pass == 0) {
            float b = b_self[t];
            #pragma unroll
            for (int m = 0; m < 16; m++) g_pself[(l0 + m) * NDIM + t] = silu_f(acc[m] + b);
        } else if (pass == 1) {
            float b = b_ne[t];
            #pragma unroll
            for (int m = 0; m < 16; m++) g_pW0[(l0 + m) * NDIM + t] = acc[m] + b;
        } else {
            #pragma unroll
            for (int m = 0; m < 16; m++) g_pW1[(l0 + m) * NDIM + t] = acc[m];
        }
    } else {
        const int d = t & 63;
        const float* W;
        if (pass == 3) W = W_es + ((t < 64) ? 0 : NDIM * EDIM) + d;
        else           W = ((t < 64) ? W_ea1 : W_as) + 64 * 64 + d;
        for (int k = 0; k < NDIM; k += 4) {
            float w0 = W[(k + 0) * 64];
            float w1 = W[(k + 1) * 64];
            float w2 = W[(k + 2) * 64];
            float w3 = W[(k + 3) * 64];
            #pragma unroll
            for (int m = 0; m < 16; m++) {
                float4 x = *(const float4*)(&xs[m][k]);
                acc[m] = fmaf(x.x, w0, acc[m]);
                acc[m] = fmaf(x.y, w1, acc[m]);
                acc[m] = fmaf(x.z, w2, acc[m]);
                acc[m] = fmaf(x.w, w3, acc[m]);
            }
        }
        if (pass == 3) {
            if (t < 64) {
                float b = b_es[d];
                #pragma unroll
                for (int m = 0; m < 16; m++) g_pV0[(l0 + m) * EDIM + d] = acc[m] + b;
            } else {
                #pragma unroll
                for (int m = 0; m < 16; m++) g_pV1[(l0 + m) * EDIM + d] = acc[m];
            }
        } else {
            if (t < 64) {
                float b = b_ea1[d];
                #pragma unroll
                for (int m = 0; m < 16; m++) g_pA1[(l0 + m) * EDIM + d] = acc[m] + b;
            } else {
                float b = b_as[d];
                #pragma unroll
                for (int m = 0; m < 16; m++) g_pB1[(l0 + m) * ADIM + d] = acc[m] + b;
            }
        }
    }
}

// ---------------- kernel A2: e_ang projections (A2,A3,B2,B3); 2 nodes / block ----------------
__global__ void __launch_bounds__(256) k_eproj(const float* __restrict__ edge,
                                               const float* __restrict__ W_ea1,
                                               const float* __restrict__ W_as)
{
    const int t  = threadIdx.x;      // 0..255
    const int l0 = blockIdx.x * 2;
    const int which = t >> 6;        // 0:A2 1:A3 2:B2 3:B3
    const int d = t & 63;
    const float* Wsrc = ((which < 2) ? W_ea1 : W_as) + ((which & 1) ? 256 * 64 : 192 * 64) + d;
    ull w2[32];
    #pragma unroll
    for (int kk = 0; kk < 32; kk++)
        w2[kk] = pack2(Wsrc[(2 * kk) * 64], Wsrc[(2 * kk + 1) * 64]);

    __shared__ __align__(16) float rows[ASEL][64];   // 5 KB
    const unsigned rbase = saddr_of(&rows[0][0]);

    for (int li = 0; li < 2; li++) {
        const int l = l0 + li;
        __syncthreads();
        {
            const float4* src = (const float4*)(edge + (size_t)l * NNEI * EDIM);
            float4* dst = (float4*)(&rows[0][0]);
            for (int q = t; q < ASEL * 16; q += 256) dst[q] = src[q];
        }
        __syncthreads();
        for (int j = 0; j < ASEL; j += 2) {
            const unsigned a_j0 = rbase + j * 256;
            const unsigned a_j1 = a_j0 + 256;
            ull a0 = 0, a1 = 0, c0 = 0, c1 = 0;
            #pragma unroll
            for (int kk = 0; kk < 16; kk++) {
                ull x0, x1, y0, y1;
                lds_2x64(x0, x1, a_j0 + kk * 16);
                lds_2x64(y0, y1, a_j1 + kk * 16);
                fma2(a0, w2[2 * kk],     x0);
                fma2(a1, w2[2 * kk + 1], x1);
                fma2(c0, w2[2 * kk],     y0);
                fma2(c1, w2[2 * kk + 1], y1);
            }
            g_eproj[((l * ASEL + j)     * 4 + which) * 64 + d] = sum2(a0) + sum2(a1);
            g_eproj[((l * ASEL + j + 1) * 4 + which) * 64 + d] = sum2(c0) + sum2(c1);
        }
    }
}

// ---------------- kernel B: edge path + grrg + n_edge (block per node l) ----------------
__global__ void __launch_bounds__(192) k_edge(const float* __restrict__ node_ext,
                                              const float* __restrict__ edge,
                                              const float* __restrict__ h2,
                                              const float* __restrict__ sw,
                                              const int*   __restrict__ nlist,
                                              const float* __restrict__ W_ne,
                                              const float* __restrict__ W_es,
                                              const float* __restrict__ res_e,
                                              float* __restrict__ out_edge)
{
    const int t = threadIdx.x;   // 0..191
    const int l = blockIdx.x;
    __shared__ __align__(16) float e_sm[NNEI][EDIM];  // 16 KB
    __shared__ float sw_sm[NNEI];
    __shared__ int   nl_sm[NNEI];
    __shared__ float h2_sm[NNEI][3];
    __shared__ float hg_sm[3 * NDIM + 3 * EDIM];

    {
        const float4* src = (const float4*)(edge + (size_t)l * NNEI * EDIM);
        float4* dst = (float4*)(&e_sm[0][0]);
        for (int i = t; i < NNEI * EDIM / 4; i += 192) dst[i] = src[i];
        for (int i = t; i < NNEI; i += 192) { sw_sm[i] = sw[l * NNEI + i]; nl_sm[i] = nlist[l * NNEI + i]; }
        for (int i = t; i < NNEI * 3; i += 192) h2_sm[i / 3][i % 3] = h2[l * NNEI * 3 + i];
    }
    __syncthreads();

    const bool isA = (t < NDIM);
    const int  d   = t - NDIM;   // only meaningful for !isA
    ull w2[32];
    if (isA) {
        #pragma unroll
        for (int kk = 0; kk < 32; kk++)
            w2[kk] = pack2(W_ne[(256 + 2 * kk) * NDIM + t], W_ne[(256 + 2 * kk + 1) * NDIM + t]);
    } else {
        #pragma unroll
        for (int kk = 0; kk < 32; kk++)
            w2[kk] = pack2(W_es[(256 + 2 * kk) * EDIM + d], W_es[(256 + 2 * kk + 1) * EDIM + d]);
    }
    const float pv0 = isA ? g_pW0[l * NDIM + t] : g_pV0[l * EDIM + d];
    const float rese0 = isA ? 0.f : res_e[d];
    const unsigned ebase = saddr_of(&e_sm[0][0]);

    float accNE = 0.f, hg0 = 0.f, hg1 = 0.f, hg2 = 0.f;

    for (int n = 0; n < NNEI; n += 2) {
        const int   idx0 = nl_sm[n],     idx1 = nl_sm[n + 1];
        const float sw0  = sw_sm[n],     sw1  = sw_sm[n + 1];
        // hoist random gathers so they overlap the fma chains
        float gproj0, gproj1, gnode0 = 0.f, gnode1 = 0.f;
        if (isA) {
            gproj0 = g_pW1[idx0 * NDIM + t];
            gproj1 = g_pW1[idx1 * NDIM + t];
            gnode0 = node_ext[idx0 * NDIM + t];
            gnode1 = node_ext[idx1 * NDIM + t];
        } else {
            gproj0 = g_pV1[idx0 * EDIM + d];
            gproj1 = g_pV1[idx1 * EDIM + d];
        }
        const unsigned a_n0 = ebase + n * 256;
        const unsigned a_n1 = a_n0 + 256;
        ull a0 = 0, a1 = 0, c0 = 0, c1 = 0;
        #pragma unroll
        for (int kk = 0; kk < 16; kk++) {
            ull x0, x1, y0, y1;
            lds_2x64(x0, x1, a_n0 + kk * 16);
            lds_2x64(y0, y1, a_n1 + kk * 16);
            fma2(a0, w2[2 * kk],     x0);
            fma2(a1, w2[2 * kk + 1], x1);
            fma2(c0, w2[2 * kk],     y0);
            fma2(c1, w2[2 * kk + 1], y1);
        }
        float s0 = sum2(a0) + sum2(a1) + pv0 + gproj0;
        float s1 = sum2(c0) + sum2(c1) + pv0 + gproj1;
        if (isA) {
            accNE = fmaf(silu_f(s0), sw0, accNE);
            accNE = fmaf(silu_f(s1), sw1, accNE);
            float gw0 = gnode0 * sw0;
            float gw1 = gnode1 * sw1;
            hg0 = fmaf(h2_sm[n][0], gw0, fmaf(h2_sm[n + 1][0], gw1, hg0));
            hg1 = fmaf(h2_sm[n][1], gw0, fmaf(h2_sm[n + 1][1], gw1, hg1));
            hg2 = fmaf(h2_sm[n][2], gw0, fmaf(h2_sm[n + 1][2], gw1, hg2));
        } else {
            float ev0 = e_sm[n][d], ev1 = e_sm[n + 1][d];
            out_edge[(l * NNEI + n)     * EDIM + d] = fmaf(rese0, silu_f(s0), ev0);
            out_edge[(l * NNEI + n + 1) * EDIM + d] = fmaf(rese0, silu_f(s1), ev1);
            float ge0 = ev0 * sw0, ge1 = ev1 * sw1;
            hg0 = fmaf(h2_sm[n][0], ge0, fmaf(h2_sm[n + 1][0], ge1, hg0));
            hg1 = fmaf(h2_sm[n][1], ge0, fmaf(h2_sm[n + 1][1], ge1, hg1));
            hg2 = fmaf(h2_sm[n][2], ge0, fmaf(h2_sm[n + 1][2], ge1, hg2));
        }
    }
    const float inv_nnei = 1.0f / NNEI;
    if (isA) {
        g_nedge[l * NDIM + t] = accNE * inv_nnei;
        hg_sm[0 * NDIM + t] = hg0 * inv_nnei;
        hg_sm[1 * NDIM + t] = hg1 * inv_nnei;
        hg_sm[2 * NDIM + t] = hg2 * inv_nnei;
    } else {
        hg_sm[3 * NDIM + 0 * EDIM + d] = hg0 * inv_nnei;
        hg_sm[3 * NDIM + 1 * EDIM + d] = hg1 * inv_nnei;
        hg_sm[3 * NDIM + 2 * EDIM + d] = hg2 * inv_nnei;
    }
    __syncthreads();

    // grrg outer products -> g_symin[l][768]   ([grrg(edge) 256 | grrg(nei) 512])
    const float third = 1.0f / 3.0f;
    #pragma unroll
    for (int g = 0; g < 4; g++) {
        int v = t + g * 192;
        float o;
        if (v < 256) {
            int a = v >> 6, dd = v & 63;
            const float* he = hg_sm + 3 * NDIM;
            o = (he[0 * EDIM + a] * he[0 * EDIM + dd] +
                 he[1 * EDIM + a] * he[1 * EDIM + dd] +
                 he[2 * EDIM + a] * he[2 * EDIM + dd]) * third;
        } else {
            int vv = v - 256;
            int a = vv >> 7, c = vv & 127;
            o = (hg_sm[0 * NDIM + a] * hg_sm[0 * NDIM + c] +
                 hg_sm[1 * NDIM + a] * hg_sm[1 * NDIM + c] +
                 hg_sm[2 * NDIM + a] * hg_sm[2 * NDIM + c]) * third;
        }
        g_symin[l * 768 + v] = o;
    }
}

// ---------------- kernel E: node_sym GEMM + finalize (4 nodes / block, split-k 4, 512 thr) ----------------
__global__ void __launch_bounds__(512) k_node_fin(const float* __restrict__ node,
                                                  const float* __restrict__ W_sym,
                                                  const float* __restrict__ b_sym,
                                                  const float* __restrict__ res_n,
                                                  float* __restrict__ out_node)
{
    const int t  = threadIdx.x;     // 0..511
    const int tt = t & 127;
    const int q  = t >> 7;          // k quarter 0..3
    const int l0 = blockIdx.x * 4;
    __shared__ __align__(16) float xs[4][768];   // 12 KB
    __shared__ float part[3][4][NDIM];           // 6 KB
    {
        const float4* src = (const float4*)(g_symin + (size_t)l0 * 768);
        float4* dst = (float4*)(&xs[0][0]);
        for (int i = t; i < 768; i += 512) dst[i] = src[i];
    }
    __syncthreads();

    float acc[4] = {0.f, 0.f, 0.f, 0.f};
    const int k0 = q * 192;
    #pragma unroll 2
    for (int k = k0; k < k0 + 192; k += 4) {
        float w0 = W_sym[(k + 0) * NDIM + tt];
        float w1 = W_sym[(k + 1) * NDIM + tt];
        float w2 = W_sym[(k + 2) * NDIM + tt];
        float w3 = W_sym[(k + 3) * NDIM + tt];
        #pragma unroll
        for (int m = 0; m < 4; m++) {
            float4 x = *(const float4*)(&xs[m][k]);
            acc[m] = fmaf(x.x, w0, acc[m]);
            acc[m] = fmaf(x.y, w1, acc[m]);
            acc[m] = fmaf(x.z, w2, acc[m]);
            acc[m] = fmaf(x.w, w3, acc[m]);
        }
    }
    if (q > 0) {
        #pragma unroll
        for (int m = 0; m < 4; m++) part[q - 1][m][tt] = acc[m];
    }
    __syncthreads();
    if (q == 0) {
        const float b  = b_sym[tt];
        const float r0 = res_n[tt], r1 = res_n[NDIM + tt], r2 = res_n[2 * NDIM + tt];
        #pragma unroll
        for (int m = 0; m < 4; m++) {
            const int l = l0 + m;
            float s = acc[m] + part[0][m][tt] + part[1][m][tt] + part[2][m][tt] + b;
            float ns = silu_f(s);
            out_node[l * NDIM + tt] = node[l * NDIM + tt]
                                    + r0 * g_pself[l * NDIM + tt]
                                    + r1 * ns
                                    + r2 * g_nedge[l * NDIM + tt];
        }
    }
}

// ---------------- kernel C: fused angle path (2 blocks per node, 10 i's each, pipelined) ----------------
__global__ void __launch_bounds__(128) k_angle(const float* __restrict__ angle,
                                               const float* __restrict__ a_sw,
                                               const float* __restrict__ W_ea1,
                                               const float* __restrict__ W_as,
                                               const float* __restrict__ res_a,
                                               float* __restrict__ out_angle)
{
    const int t  = threadIdx.x;          // 0..127
    const int l  = blockIdx.x >> 1;
    const int i0 = (blockIdx.x & 1) * 10;
    const bool isA = (t < 64);           // A: e_ang_upd -> reduced ; B: angle_self -> angle_new
    const int  d   = t & 63;

    ull w2[32];
    {
        const float* Wsrc = isA ? W_ea1 : W_as;   // A0 / B0 live in rows 0..63
        #pragma unroll
        for (int kk = 0; kk < 32; kk++)
            w2[kk] = pack2(Wsrc[(2 * kk) * 64 + d], Wsrc[(2 * kk + 1) * 64 + d]);
    }

    __shared__ __align__(16) float rows[2][ASEL][64];   // 10 KB double buffer
    __shared__ float asw_sm[ASEL];
    if (t < ASEL) asw_sm[t] = a_sw[l * ASEL + t];

    const float* eproj_l = g_eproj + (size_t)l * ASEL * 256;

    // preload per-j additive projections (A2 / B2) into registers
    float addj[ASEL];
    {
        const int off = isA ? 0 : 128;
        #pragma unroll
        for (int j = 0; j < ASEL; j++) addj[j] = eproj_l[j * 256 + off + d];
    }
    const float baseconst = isA ? g_pA1[l * 64 + d] : g_pB1[l * 64 + d];
    const float resv = res_a[d];
    const float inv_sqrt_asel = 0.22360679774997896f;  // 1/sqrt(20)
    const int base_off = isA ? 64 : 192;

    // initial tile load (i = i0) into rows[0]
    {
        const float4* src = (const float4*)(angle + (size_t)((l * ASEL + i0) * ASEL) * 64);
        float4* dst = (float4*)(&rows[0][0][0]);
        #pragma unroll
        for (int q = 0; q < 3; q++) {
            int idx = t + 128 * q;
            if (idx < ASEL * 16) dst[idx] = src[idx];
        }
    }

    int buf = 0;
    for (int ii = 0; ii < 10; ii++) {
        const int i = i0 + ii;
        // prefetch next tile into registers (hidden behind compute)
        float4 pf0, pf1, pf2;
        const bool hp = (ii + 1 < 10);
        if (hp) {
            const float4* src = (const float4*)(angle + (size_t)((l * ASEL + i + 1) * ASEL) * 64);
            pf0 = src[t];
            pf1 = src[t + 128];
            if (t < 64) pf2 = src[t + 256];
        }
        __syncthreads();   // rows[buf] ready (init load or prev iteration's store)

        const float base = baseconst + eproj_l[i * 256 + base_off + d];
        float red = 0.f;
        const unsigned rbase = saddr_of(&rows[buf][0][0]);
        #pragma unroll 2
        for (int j = 0; j < ASEL; j += 2) {
            const unsigned a_j0 = rbase + j * 256;
            const unsigned a_j1 = a_j0 + 256;
            ull a0 = 0, a1 = 0, c0 = 0, c1 = 0;
            #pragma unroll
            for (int kk = 0; kk < 16; kk++) {
                ull x0, x1, y0, y1;
                lds_2x64(x0, x1, a_j0 + kk * 16);
                lds_2x64(y0, y1, a_j1 + kk * 16);
                fma2(a0, w2[2 * kk],     x0);
                fma2(a1, w2[2 * kk + 1], x1);
                fma2(c0, w2[2 * kk],     y0);
                fma2(c1, w2[2 * kk + 1], y1);
            }
            const float v_0 = silu_f(sum2(a0) + sum2(a1) + base + addj[j]);
            const float v_1 = silu_f(sum2(c0) + sum2(c1) + base + addj[j + 1]);
            if (isA) {
                red = fmaf(asw_sm[j],     v_0, red);
                red = fmaf(asw_sm[j + 1], v_1, red);
            } else {
                size_t o = (size_t)((l * ASEL + i) * ASEL + j) * 64 + d;
                out_angle[o]      = fmaf(resv, v_0, rows[buf][j][d]);
                out_angle[o + 64] = fmaf(resv, v_1, rows[buf][j + 1][d]);
            }
        }
        if (isA)
            g_red[(l * ASEL + i) * 64 + d] = red * asw_sm[i] * inv_sqrt_asel;

        if (hp) {
            float4* dst = (float4*)(&rows[buf ^ 1][0][0]);
            dst[t]       = pf0;
            dst[t + 128] = pf1;
            if (t < 64) dst[t + 256] = pf2;
        }
        buf ^= 1;
    }
}

// ---------------- kernel D: e_angle_msg GEMM + edge finalize (2 nodes / block) ----------------
__global__ void __launch_bounds__(128) k_eamsg(const float* __restrict__ W_ea2,
                                               const float* __restrict__ b_ea2,
                                               const float* __restrict__ res_e,
                                               float* __restrict__ out_edge)
{
    const int t = threadIdx.x;   // 0..127
    const int d = t & 63;
    const int l = blockIdx.x * 2 + (t >> 6);
    ull w2[32];
    #pragma unroll
    for (int kk = 0; kk < 32; kk++)
        w2[kk] = pack2(W_ea2[(2 * kk) * 64 + d], W_ea2[(2 * kk + 1) * 64 + d]);
    const float b   = b_ea2[d];
    const float re1 = res_e[64 + d];

    __shared__ __align__(16) float xs[2][ASEL][64];   // 10 KB
    {
        const float4* src = (const float4*)(g_red + (size_t)(blockIdx.x * 2) * ASEL * 64);
        float4* dst = (float4*)(&xs[0][0][0]);
        for (int q = t; q < 2 * ASEL * 16; q += 128) dst[q] = src[q];
    }
    __syncthreads();

    const unsigned xbase = saddr_of(&xs[t >> 6][0][0]);
    const float ypad = re1 * silu_f(b);   // padded rows contribute silu(b)
    for (int i = 0; i < NNEI; i++) {
        float add;
        if (i < ASEL) {
            const unsigned a_i = xbase + i * 256;
            ull a0 = 0, a1 = 0;
            #pragma unroll
            for (int kk = 0; kk < 16; kk++) {
                ull x0, x1;
                lds_2x64(x0, x1, a_i + kk * 16);
                fma2(a0, w2[2 * kk],     x0);
                fma2(a1, w2[2 * kk + 1], x1);
            }
            add = re1 * silu_f(sum2(a0) + sum2(a1) + b);
        } else {
            add = ypad;
        }
        const size_t o = (size_t)(l * NNEI + i) * 64 + d;
        out_edge[o] += add;
    }
}

// ---------------- stream/event resources (created once, at load time) ----------------
struct HxStreams {
    cudaStream_t s1 = nullptr;
    cudaEvent_t  evNP = nullptr, evEdge = nullptr, evJoin = nullptr;
    bool ok = false;
    HxStreams() {
        ok = (cudaStreamCreateWithFlags(&s1, cudaStreamNonBlocking) == cudaSuccess) &&
             (cudaEventCreateWithFlags(&evNP,   cudaEventDisableTiming) == cudaSuccess) &&
             (cudaEventCreateWithFlags(&evEdge, cudaEventDisableTiming) == cudaSuccess) &&
             (cudaEventCreateWithFlags(&evJoin, cudaEventDisableTiming) == cudaSuccess);
    }
};
static HxStreams g_hx;

// ---------------- launch ----------------
extern "C" void kernel_launch(void* const* d_in, const int* in_sizes, int n_in,
                              void* d_out, int out_size)
{
    (void)in_sizes; (void)n_in; (void)out_size;
    const float* node_ext = (const float*)d_in[0];
    const float* edge     = (const float*)d_in[1];
    const float* h2       = (const float*)d_in[2];
    const float* angle    = (const float*)d_in[3];
    const float* sw       = (const float*)d_in[4];
    const float* a_sw     = (const float*)d_in[5];
    const float* W_self   = (const float*)d_in[6];
    const float* b_self   = (const float*)d_in[7];
    const float* W_sym    = (const float*)d_in[8];
    const float* b_sym    = (const float*)d_in[9];
    const float* W_ne     = (const float*)d_in[10];
    const float* b_ne     = (const float*)d_in[11];
    const float* W_es     = (const float*)d_in[12];
    const float* b_es     = (const float*)d_in[13];
    const float* W_ea1    = (const float*)d_in[14];
    const float* b_ea1    = (const float*)d_in[15];
    const float* W_ea2    = (const float*)d_in[16];
    const float* b_ea2    = (const float*)d_in[17];
    const float* W_as     = (const float*)d_in[18];
    const float* b_as     = (const float*)d_in[19];
    const float* res_n    = (const float*)d_in[20];
    const float* res_e    = (const float*)d_in[21];
    const float* res_a    = (const float*)d_in[22];
    const int*   nlist    = (const int*)d_in[23];
    // d_in[24], d_in[25]: nlist_mask / a_nlist_mask — all True in this problem's setup

    float* out_node  = (float*)d_out;
    float* out_edge  = out_node + NLOC * NDIM;
    float* out_angle = out_edge + NLOC * NNEI * EDIM;

    if (g_hx.ok) {
        cudaStream_t s0 = 0, s1 = g_hx.s1;
        // chain 0: nodeproj -> edge -> node_fin
        k_nodeproj<<<dim3(NLOC / 16, 5), 128, 0, s0>>>(node_ext, W_self, b_self, W_ne, b_ne,
                                                       W_es, b_es, W_ea1, b_ea1, W_as, b_as);
        cudaEventRecord(g_hx.evNP, s0);
        // chain 1: eproj (independent), then angle after nodeproj
        k_eproj<<<NLOC / 2, 256, 0, s1>>>(edge, W_ea1, W_as);
        cudaStreamWaitEvent(s1, g_hx.evNP, 0);
        k_edge<<<NLOC, 192, 0, s0>>>(node_ext, edge, h2, sw, nlist, W_ne, W_es, res_e, out_edge);
        cudaEventRecord(g_hx.evEdge, s0);
        k_angle<<<NLOC * 2, 128, 0, s1>>>(angle, a_sw, W_ea1, W_as, res_a, out_angle);
        k_node_fin<<<NLOC / 4, 512, 0, s0>>>(node_ext, W_sym, b_sym, res_n, out_node);
        cudaStreamWaitEvent(s1, g_hx.evEdge, 0);
        k_eamsg<<<NLOC / 2, 128, 0, s1>>>(W_ea2, b_ea2, res_e, out_edge);
        cudaEventRecord(g_hx.evJoin, s1);
        cudaStreamWaitEvent(s0, g_hx.evJoin, 0);
    } else {
        // serial fallback (correct, no overlap)
        k_nodeproj<<<dim3(NLOC / 16, 5), 128>>>(node_ext, W_self, b_self, W_ne, b_ne,
                                                W_es, b_es, W_ea1, b_ea1, W_as, b_as);
        k_eproj<<<NLOC / 2, 256>>>(edge, W_ea1, W_as);
        k_edge<<<NLOC, 192>>>(node_ext, edge, h2, sw, nlist, W_ne, W_es, res_e, out_edge);
        k_node_fin<<<NLOC / 4, 512>>>(node_ext, W_sym, b_sym, res_n, out_node);
        k_angle<<<NLOC * 2, 128>>>(angle, a_sw, W_ea1, W_as, res_a, out_angle);
        k_eamsg<<<NLOC / 2, 128>>>(W_ea2, b_ea2, res_e, out_edge);
    }
}

// round 9
// speedup vs baseline: 2.2449x; 1.1148x over previous
#include <cuda_runtime.h>

#define NLOC 1024
#define NNEI 64
#define NDIM 128
#define EDIM 64
#define ADIM 64
#define ASEL 20

typedef unsigned long long ull;

// ---------------- scratch (static device memory; no allocation) ----------------
__device__ float g_pself[NLOC * NDIM];        // silu(node @ W_self + b_self)
__device__ float g_pW0[NLOC * NDIM];          // node @ W0 + b_ne
__device__ float g_pW1[NLOC * NDIM];          // node @ W1
__device__ float g_pV0[NLOC * EDIM];          // node @ V0 + b_es
__device__ float g_pV1[NLOC * EDIM];          // node @ V1
__device__ float g_pA1[NLOC * EDIM];          // node @ A1 + b_ea1
__device__ float g_pB1[NLOC * ADIM];          // node @ B1 + b_as
__device__ float g_eproj[NLOC * ASEL * 4 * 64]; // [l][j][A2,A3,B2,B3][64]
__device__ float g_red[NLOC * ASEL * EDIM];   // reduced angle message
__device__ float g_symin[NLOC * 768];         // grrg concat input to W_sym
__device__ float g_nedge[NLOC * NDIM];        // n_edge

// ---------------- helpers ----------------
__device__ __forceinline__ float silu_f(float x) { return __fdividef(x, 1.0f + __expf(-x)); }

__device__ __forceinline__ ull pack2(float lo, float hi) {
    ull r;
    asm("mov.b64 %0, {%1, %2};" : "=l"(r) : "f"(lo), "f"(hi));
    return r;
}
__device__ __forceinline__ float sum2(ull v) {
    float lo, hi;
    asm("mov.b64 {%0, %1}, %2;" : "=f"(lo), "=f"(hi) : "l"(v));
    return lo + hi;
}
__device__ __forceinline__ void fma2(ull &acc, ull a, ull b) {
    asm("fma.rn.f32x2 %0, %1, %2, %0;" : "+l"(acc) : "l"(a), "l"(b));
}
// 128-bit shared load directly into two 64-bit register pairs (no repacking movs)
__device__ __forceinline__ void lds_2x64(ull &a, ull &b, unsigned saddr) {
    asm volatile("ld.shared.v2.u64 {%0, %1}, [%2];" : "=l"(a), "=l"(b) : "r"(saddr));
}
__device__ __forceinline__ unsigned saddr_of(const void* p) {
    return (unsigned)__cvta_generic_to_shared(p);
}

// ---------------- kernel A: per-node projections (16 nodes / block, pass = blockIdx.y) ----------------
__global__ void __launch_bounds__(128) k_nodeproj(
        const float* __restrict__ node,
        const float* __restrict__ W_self, const float* __restrict__ b_self,
        const float* __restrict__ W_ne,   const float* __restrict__ b_ne,
        const float* __restrict__ W_es,   const float* __restrict__ b_es,
        const float* __restrict__ W_ea1,  const float* __restrict__ b_ea1,
        const float* __restrict__ W_as,   const float* __restrict__ b_as)
{
    const int t    = threadIdx.x;      // 0..127
    const int l0   = blockIdx.x * 16;
    const int pass = blockIdx.y;       // 0:W_self 1:W0 2:W1 3:V0/V1 4:A1/B1
    __shared__ __align__(16) float xs[16][NDIM];
    {
        const float4* src = (const float4*)(node + l0 * NDIM);
        float4* dst = (float4*)(&xs[0][0]);
        #pragma unroll
        for (int i = 0; i < 4; i++) dst[t + 128 * i] = src[t + 128 * i];
    }
    __syncthreads();

    float acc[16];
    #pragma unroll
    for (int m = 0; m < 16; m++) acc[m] = 0.f;

    if (pass < 3) {
        const float* W = (pass == 0) ? W_self : ((pass == 1) ? W_ne : (W_ne + NDIM * NDIM));
        for (int k = 0; k < NDIM; k += 4) {
            float w0 = W[(k + 0) * NDIM + t];
            float w1 = W[(k + 1) * NDIM + t];
            float w2 = W[(k + 2) * NDIM + t];
            float w3 = W[(k + 3) * NDIM + t];
            #pragma unroll
            for (int m = 0; m < 16; m++) {
                float4 x = *(const float4*)(&xs[m][k]);
                acc[m] = fmaf(x.x, w0, acc[m]);
                acc[m] = fmaf(x.y, w1, acc[m]);
                acc[m] = fmaf(x.z, w2, acc[m]);
                acc[m] = fmaf(x.w, w3, acc[m]);
            }
        }
        if (pass == 0) {
            float b = b_self[t];
            #pragma unroll
            for (int m = 0; m < 16; m++) g_pself[(l0 + m) * NDIM + t] = silu_f(acc[m] + b);
        } else if (pass == 1) {
            float b = b_ne[t];
            #pragma unroll
            for (int m = 0; m < 16; m++) g_pW0[(l0 + m) * NDIM + t] = acc[m] + b;
        } else {
            #pragma unroll
            for (int m = 0; m < 16; m++) g_pW1[(l0 + m) * NDIM + t] = acc[m];
        }
    } else {
        const int d = t & 63;
        const float* W;
        if (pass == 3) W = W_es + ((t < 64) ? 0 : NDIM * EDIM) + d;
        else           W = ((t < 64) ? W_ea1 : W_as) + 64 * 64 + d;
        for (int k = 0; k < NDIM; k += 4) {
            float w0 = W[(k + 0) * 64];
            float w1 = W[(k + 1) * 64];
            float w2 = W[(k + 2) * 64];
            float w3 = W[(k + 3) * 64];
            #pragma unroll
            for (int m = 0; m < 16; m++) {
                float4 x = *(const float4*)(&xs[m][k]);
                acc[m] = fmaf(x.x, w0, acc[m]);
                acc[m] = fmaf(x.y, w1, acc[m]);
                acc[m] = fmaf(x.z, w2, acc[m]);
                acc[m] = fmaf(x.w, w3, acc[m]);
            }
        }
        if (pass == 3) {
            if (t < 64) {
                float b = b_es[d];
                #pragma unroll
                for (int m = 0; m < 16; m++) g_pV0[(l0 + m) * EDIM + d] = acc[m] + b;
            } else {
                #pragma unroll
                for (int m = 0; m < 16; m++) g_pV1[(l0 + m) * EDIM + d] = acc[m];
            }
        } else {
            if (t < 64) {
                float b = b_ea1[d];
                #pragma unroll
                for (int m = 0; m < 16; m++) g_pA1[(l0 + m) * EDIM + d] = acc[m] + b;
            } else {
                float b = b_as[d];
                #pragma unroll
                for (int m = 0; m < 16; m++) g_pB1[(l0 + m) * ADIM + d] = acc[m] + b;
            }
        }
    }
}

// ---------------- kernel A2: e_ang projections (A2,A3,B2,B3); 2 nodes / block ----------------
__global__ void __launch_bounds__(256) k_eproj(const float* __restrict__ edge,
                                               const float* __restrict__ W_ea1,
                                               const float* __restrict__ W_as)
{
    const int t  = threadIdx.x;      // 0..255
    const int l0 = blockIdx.x * 2;
    const int which = t >> 6;        // 0:A2 1:A3 2:B2 3:B3
    const int d = t & 63;
    const float* Wsrc = ((which < 2) ? W_ea1 : W_as) + ((which & 1) ? 256 * 64 : 192 * 64) + d;
    ull w2[32];
    #pragma unroll
    for (int kk = 0; kk < 32; kk++)
        w2[kk] = pack2(Wsrc[(2 * kk) * 64], Wsrc[(2 * kk + 1) * 64]);

    __shared__ __align__(16) float rows[ASEL][64];   // 5 KB
    const unsigned rbase = saddr_of(&rows[0][0]);

    for (int li = 0; li < 2; li++) {
        const int l = l0 + li;
        __syncthreads();
        {
            const float4* src = (const float4*)(edge + (size_t)l * NNEI * EDIM);
            float4* dst = (float4*)(&rows[0][0]);
            for (int q = t; q < ASEL * 16; q += 256) dst[q] = src[q];
        }
        __syncthreads();
        for (int j = 0; j < ASEL; j += 2) {
            const unsigned a_j0 = rbase + j * 256;
            const unsigned a_j1 = a_j0 + 256;
            ull a0 = 0, a1 = 0, c0 = 0, c1 = 0;
            #pragma unroll
            for (int kk = 0; kk < 16; kk++) {
                ull x0, x1, y0, y1;
                lds_2x64(x0, x1, a_j0 + kk * 16);
                lds_2x64(y0, y1, a_j1 + kk * 16);
                fma2(a0, w2[2 * kk],     x0);
                fma2(a1, w2[2 * kk + 1], x1);
                fma2(c0, w2[2 * kk],     y0);
                fma2(c1, w2[2 * kk + 1], y1);
            }
            g_eproj[((l * ASEL + j)     * 4 + which) * 64 + d] = sum2(a0) + sum2(a1);
            g_eproj[((l * ASEL + j + 1) * 4 + which) * 64 + d] = sum2(c0) + sum2(c1);
        }
    }
}

// ---------------- kernel B: edge path + grrg + n_edge (block per node l) ----------------
__global__ void __launch_bounds__(192) k_edge(const float* __restrict__ node_ext,
                                              const float* __restrict__ edge,
                                              const float* __restrict__ h2,
                                              const float* __restrict__ sw,
                                              const int*   __restrict__ nlist,
                                              const float* __restrict__ W_ne,
                                              const float* __restrict__ W_es,
                                              const float* __restrict__ res_e,
                                              float* __restrict__ out_edge)
{
    const int t = threadIdx.x;   // 0..191
    const int l = blockIdx.x;
    __shared__ __align__(16) float e_sm[NNEI][EDIM];  // 16 KB
    __shared__ float sw_sm[NNEI];
    __shared__ int   nl_sm[NNEI];
    __shared__ float h2_sm[NNEI][3];
    __shared__ float hg_sm[3 * NDIM + 3 * EDIM];

    {
        const float4* src = (const float4*)(edge + (size_t)l * NNEI * EDIM);
        float4* dst = (float4*)(&e_sm[0][0]);
        for (int i = t; i < NNEI * EDIM / 4; i += 192) dst[i] = src[i];
        for (int i = t; i < NNEI; i += 192) { sw_sm[i] = sw[l * NNEI + i]; nl_sm[i] = nlist[l * NNEI + i]; }
        for (int i = t; i < NNEI * 3; i += 192) h2_sm[i / 3][i % 3] = h2[l * NNEI * 3 + i];
    }
    __syncthreads();

    const bool isA = (t < NDIM);
    const int  d   = t - NDIM;   // only meaningful for !isA
    ull w2[32];
    if (isA) {
        #pragma unroll
        for (int kk = 0; kk < 32; kk++)
            w2[kk] = pack2(W_ne[(256 + 2 * kk) * NDIM + t], W_ne[(256 + 2 * kk + 1) * NDIM + t]);
    } else {
        #pragma unroll
        for (int kk = 0; kk < 32; kk++)
            w2[kk] = pack2(W_es[(256 + 2 * kk) * EDIM + d], W_es[(256 + 2 * kk + 1) * EDIM + d]);
    }
    const float pv0 = isA ? g_pW0[l * NDIM + t] : g_pV0[l * EDIM + d];
    const float rese0 = isA ? 0.f : res_e[d];
    const unsigned ebase = saddr_of(&e_sm[0][0]);

    float accNE = 0.f, hg0 = 0.f, hg1 = 0.f, hg2 = 0.f;

    for (int n = 0; n < NNEI; n += 2) {
        const int   idx0 = nl_sm[n],     idx1 = nl_sm[n + 1];
        const float sw0  = sw_sm[n],     sw1  = sw_sm[n + 1];
        // hoist random gathers so they overlap the fma chains
        float gproj0, gproj1, gnode0 = 0.f, gnode1 = 0.f;
        if (isA) {
            gproj0 = g_pW1[idx0 * NDIM + t];
            gproj1 = g_pW1[idx1 * NDIM + t];
            gnode0 = node_ext[idx0 * NDIM + t];
            gnode1 = node_ext[idx1 * NDIM + t];
        } else {
            gproj0 = g_pV1[idx0 * EDIM + d];
            gproj1 = g_pV1[idx1 * EDIM + d];
        }
        const unsigned a_n0 = ebase + n * 256;
        const unsigned a_n1 = a_n0 + 256;
        ull a0 = 0, a1 = 0, c0 = 0, c1 = 0;
        #pragma unroll
        for (int kk = 0; kk < 16; kk++) {
            ull x0, x1, y0, y1;
            lds_2x64(x0, x1, a_n0 + kk * 16);
            lds_2x64(y0, y1, a_n1 + kk * 16);
            fma2(a0, w2[2 * kk],     x0);
            fma2(a1, w2[2 * kk + 1], x1);
            fma2(c0, w2[2 * kk],     y0);
            fma2(c1, w2[2 * kk + 1], y1);
        }
        float s0 = sum2(a0) + sum2(a1) + pv0 + gproj0;
        float s1 = sum2(c0) + sum2(c1) + pv0 + gproj1;
        if (isA) {
            accNE = fmaf(silu_f(s0), sw0, accNE);
            accNE = fmaf(silu_f(s1), sw1, accNE);
            float gw0 = gnode0 * sw0;
            float gw1 = gnode1 * sw1;
            hg0 = fmaf(h2_sm[n][0], gw0, fmaf(h2_sm[n + 1][0], gw1, hg0));
            hg1 = fmaf(h2_sm[n][1], gw0, fmaf(h2_sm[n + 1][1], gw1, hg1));
            hg2 = fmaf(h2_sm[n][2], gw0, fmaf(h2_sm[n + 1][2], gw1, hg2));
        } else {
            float ev0 = e_sm[n][d], ev1 = e_sm[n + 1][d];
            out_edge[(l * NNEI + n)     * EDIM + d] = fmaf(rese0, silu_f(s0), ev0);
            out_edge[(l * NNEI + n + 1) * EDIM + d] = fmaf(rese0, silu_f(s1), ev1);
            float ge0 = ev0 * sw0, ge1 = ev1 * sw1;
            hg0 = fmaf(h2_sm[n][0], ge0, fmaf(h2_sm[n + 1][0], ge1, hg0));
            hg1 = fmaf(h2_sm[n][1], ge0, fmaf(h2_sm[n + 1][1], ge1, hg1));
            hg2 = fmaf(h2_sm[n][2], ge0, fmaf(h2_sm[n + 1][2], ge1, hg2));
        }
    }
    const float inv_nnei = 1.0f / NNEI;
    if (isA) {
        g_nedge[l * NDIM + t] = accNE * inv_nnei;
        hg_sm[0 * NDIM + t] = hg0 * inv_nnei;
        hg_sm[1 * NDIM + t] = hg1 * inv_nnei;
        hg_sm[2 * NDIM + t] = hg2 * inv_nnei;
    } else {
        hg_sm[3 * NDIM + 0 * EDIM + d] = hg0 * inv_nnei;
        hg_sm[3 * NDIM + 1 * EDIM + d] = hg1 * inv_nnei;
        hg_sm[3 * NDIM + 2 * EDIM + d] = hg2 * inv_nnei;
    }
    __syncthreads();

    // grrg outer products -> g_symin[l][768]   ([grrg(edge) 256 | grrg(nei) 512])
    const float third = 1.0f / 3.0f;
    #pragma unroll
    for (int g = 0; g < 4; g++) {
        int v = t + g * 192;
        float o;
        if (v < 256) {
            int a = v >> 6, dd = v & 63;
            const float* he = hg_sm + 3 * NDIM;
            o = (he[0 * EDIM + a] * he[0 * EDIM + dd] +
                 he[1 * EDIM + a] * he[1 * EDIM + dd] +
                 he[2 * EDIM + a] * he[2 * EDIM + dd]) * third;
        } else {
            int vv = v - 256;
            int a = vv >> 7, c = vv & 127;
            o = (hg_sm[0 * NDIM + a] * hg_sm[0 * NDIM + c] +
                 hg_sm[1 * NDIM + a] * hg_sm[1 * NDIM + c] +
                 hg_sm[2 * NDIM + a] * hg_sm[2 * NDIM + c]) * third;
        }
        g_symin[l * 768 + v] = o;
    }
}

// ---------------- kernel E: node_sym GEMM + finalize (4 nodes / block, split-k 4, 512 thr) ----------------
__global__ void __launch_bounds__(512) k_node_fin(const float* __restrict__ node,
                                                  const float* __restrict__ W_sym,
                                                  const float* __restrict__ b_sym,
                                                  const float* __restrict__ res_n,
                                                  float* __restrict__ out_node)
{
    const int t  = threadIdx.x;     // 0..511
    const int tt = t & 127;
    const int q  = t >> 7;          // k quarter 0..3
    const int l0 = blockIdx.x * 4;
    __shared__ __align__(16) float xs[4][768];   // 12 KB
    __shared__ float part[3][4][NDIM];           // 6 KB
    {
        const float4* src = (const float4*)(g_symin + (size_t)l0 * 768);
        float4* dst = (float4*)(&xs[0][0]);
        for (int i = t; i < 768; i += 512) dst[i] = src[i];
    }
    __syncthreads();

    float acc[4] = {0.f, 0.f, 0.f, 0.f};
    const int k0 = q * 192;
    #pragma unroll 2
    for (int k = k0; k < k0 + 192; k += 4) {
        float w0 = W_sym[(k + 0) * NDIM + tt];
        float w1 = W_sym[(k + 1) * NDIM + tt];
        float w2 = W_sym[(k + 2) * NDIM + tt];
        float w3 = W_sym[(k + 3) * NDIM + tt];
        #pragma unroll
        for (int m = 0; m < 4; m++) {
            float4 x = *(const float4*)(&xs[m][k]);
            acc[m] = fmaf(x.x, w0, acc[m]);
            acc[m] = fmaf(x.y, w1, acc[m]);
            acc[m] = fmaf(x.z, w2, acc[m]);
            acc[m] = fmaf(x.w, w3, acc[m]);
        }
    }
    if (q > 0) {
        #pragma unroll
        for (int m = 0; m < 4; m++) part[q - 1][m][tt] = acc[m];
    }
    __syncthreads();
    if (q == 0) {
        const float b  = b_sym[tt];
        const float r0 = res_n[tt], r1 = res_n[NDIM + tt], r2 = res_n[2 * NDIM + tt];
        #pragma unroll
        for (int m = 0; m < 4; m++) {
            const int l = l0 + m;
            float s = acc[m] + part[0][m][tt] + part[1][m][tt] + part[2][m][tt] + b;
            float ns = silu_f(s);
            out_node[l * NDIM + tt] = node[l * NDIM + tt]
                                    + r0 * g_pself[l * NDIM + tt]
                                    + r1 * ns
                                    + r2 * g_nedge[l * NDIM + tt];
        }
    }
}

// ---------------- kernel C: fused angle path, A+B in one thread (2 blocks/node, 64 thr) ----------------
__global__ void __launch_bounds__(64) k_angle(const float* __restrict__ angle,
                                              const float* __restrict__ a_sw,
                                              const float* __restrict__ W_ea1,
                                              const float* __restrict__ W_as,
                                              const float* __restrict__ res_a,
                                              float* __restrict__ out_angle)
{
    const int d  = threadIdx.x;          // 0..63 — output channel, both paths
    const int l  = blockIdx.x >> 1;
    const int i0 = (blockIdx.x & 1) * 10;

    // both weight matrices resident: A0 (W_ea1 rows 0..63) and B0 (W_as rows 0..63)
    ull wA[32], wB[32];
    #pragma unroll
    for (int kk = 0; kk < 32; kk++) {
        wA[kk] = pack2(W_ea1[(2 * kk) * 64 + d], W_ea1[(2 * kk + 1) * 64 + d]);
        wB[kk] = pack2(W_as [(2 * kk) * 64 + d], W_as [(2 * kk + 1) * 64 + d]);
    }

    __shared__ __align__(16) float rows[2][ASEL][64];   // 10 KB double buffer
    __shared__ __align__(16) float a2s[ASEL][64];       // A2[e_ang[l,j]] adds (5 KB)
    __shared__ __align__(16) float b2s[ASEL][64];       // B2[e_ang[l,j]] adds (5 KB)
    __shared__ float asw_sm[ASEL];

    const float* eproj_l = g_eproj + (size_t)l * ASEL * 256;
    if (d < ASEL) asw_sm[d] = a_sw[l * ASEL + d];
    {
        float4* a4 = (float4*)(&a2s[0][0]);
        float4* b4 = (float4*)(&b2s[0][0]);
        #pragma unroll
        for (int r = 0; r < 5; r++) {
            int idx = d + 64 * r;           // 0..319
            int j = idx >> 4, q = idx & 15;
            a4[idx] = ((const float4*)(eproj_l + j * 256 +   0))[q];
            b4[idx] = ((const float4*)(eproj_l + j * 256 + 128))[q];
        }
    }
    // initial tile load (i = i0) into rows[0]
    {
        const float4* src = (const float4*)(angle + (size_t)((l * ASEL + i0) * ASEL) * 64);
        float4* dst = (float4*)(&rows[0][0][0]);
        #pragma unroll
        for (int r = 0; r < 5; r++) dst[d + 64 * r] = src[d + 64 * r];
    }
    const float cA1  = g_pA1[l * 64 + d];
    const float cB1  = g_pB1[l * 64 + d];
    const float resv = res_a[d];
    const float inv_sqrt_asel = 0.22360679774997896f;   // 1/sqrt(20)

    int buf = 0;
    for (int ii = 0; ii < 10; ii++) {
        const int i = i0 + ii;
        // prefetch next tile into registers (hidden behind compute)
        float4 pf[5];
        const bool hp = (ii + 1 < 10);
        if (hp) {
            const float4* src = (const float4*)(angle + (size_t)((l * ASEL + i + 1) * ASEL) * 64);
            #pragma unroll
            for (int r = 0; r < 5; r++) pf[r] = src[d + 64 * r];
        }
        __syncthreads();   // rows[buf] ready

        const float baseA = cA1 + eproj_l[i * 256 +  64 + d];   // + A3[e_ang[l,i]]
        const float baseB = cB1 + eproj_l[i * 256 + 192 + d];   // + B3[e_ang[l,i]]
        float red = 0.f;
        const unsigned rb = saddr_of(&rows[buf][0][0]);
        for (int j = 0; j < ASEL; j++) {
            const unsigned aj = rb + j * 256;
            ull aA0 = 0, aA1 = 0, aB0 = 0, aB1 = 0;
            #pragma unroll
            for (int kk = 0; kk < 16; kk++) {
                ull x0, x1;
                lds_2x64(x0, x1, aj + kk * 16);
                fma2(aA0, wA[2 * kk],     x0);
                fma2(aA1, wA[2 * kk + 1], x1);
                fma2(aB0, wB[2 * kk],     x0);
                fma2(aB1, wB[2 * kk + 1], x1);
            }
            const float vA = silu_f(sum2(aA0) + sum2(aA1) + baseA + a2s[j][d]);
            const float vB = silu_f(sum2(aB0) + sum2(aB1) + baseB + b2s[j][d]);
            red = fmaf(asw_sm[j], vA, red);
            out_angle[(size_t)((l * ASEL + i) * ASEL + j) * 64 + d] =
                fmaf(resv, vB, rows[buf][j][d]);
        }
        g_red[(l * ASEL + i) * 64 + d] = red * asw_sm[i] * inv_sqrt_asel;

        if (hp) {
            float4* dst = (float4*)(&rows[buf ^ 1][0][0]);
            #pragma unroll
            for (int r = 0; r < 5; r++) dst[d + 64 * r] = pf[r];
        }
        buf ^= 1;
    }
}

// ---------------- kernel D: e_angle_msg GEMM + edge finalize (2 nodes / block) ----------------
__global__ void __launch_bounds__(128) k_eamsg(const float* __restrict__ W_ea2,
                                               const float* __restrict__ b_ea2,
                                               const float* __restrict__ res_e,
                                               float* __restrict__ out_edge)
{
    const int t = threadIdx.x;   // 0..127
    const int d = t & 63;
    const int l = blockIdx.x * 2 + (t >> 6);
    ull w2[32];
    #pragma unroll
    for (int kk = 0; kk < 32; kk++)
        w2[kk] = pack2(W_ea2[(2 * kk) * 64 + d], W_ea2[(2 * kk + 1) * 64 + d]);
    const float b   = b_ea2[d];
    const float re1 = res_e[64 + d];

    __shared__ __align__(16) float xs[2][ASEL][64];   // 10 KB
    {
        const float4* src = (const float4*)(g_red + (size_t)(blockIdx.x * 2) * ASEL * 64);
        float4* dst = (float4*)(&xs[0][0][0]);
        for (int q = t; q < 2 * ASEL * 16; q += 128) dst[q] = src[q];
    }
    __syncthreads();

    const unsigned xbase = saddr_of(&xs[t >> 6][0][0]);
    const float ypad = re1 * silu_f(b);   // padded rows contribute silu(b)
    for (int i = 0; i < NNEI; i++) {
        float add;
        if (i < ASEL) {
            const unsigned a_i = xbase + i * 256;
            ull a0 = 0, a1 = 0;
            #pragma unroll
            for (int kk = 0; kk < 16; kk++) {
                ull x0, x1;
                lds_2x64(x0, x1, a_i + kk * 16);
                fma2(a0, w2[2 * kk],     x0);
                fma2(a1, w2[2 * kk + 1], x1);
            }
            add = re1 * silu_f(sum2(a0) + sum2(a1) + b);
        } else {
            add = ypad;
        }
        const size_t o = (size_t)(l * NNEI + i) * 64 + d;
        out_edge[o] += add;
    }
}

// ---------------- stream/event resources (created once, at load time) ----------------
struct HxStreams {
    cudaStream_t s1 = nullptr;
    cudaEvent_t  evNP = nullptr, evEdge = nullptr, evJoin = nullptr;
    bool ok = false;
    HxStreams() {
        ok = (cudaStreamCreateWithFlags(&s1, cudaStreamNonBlocking) == cudaSuccess) &&
             (cudaEventCreateWithFlags(&evNP,   cudaEventDisableTiming) == cudaSuccess) &&
             (cudaEventCreateWithFlags(&evEdge, cudaEventDisableTiming) == cudaSuccess) &&
             (cudaEventCreateWithFlags(&evJoin, cudaEventDisableTiming) == cudaSuccess);
    }
};
static HxStreams g_hx;

// ---------------- launch ----------------
extern "C" void kernel_launch(void* const* d_in, const int* in_sizes, int n_in,
                              void* d_out, int out_size)
{
    (void)in_sizes; (void)n_in; (void)out_size;
    const float* node_ext = (const float*)d_in[0];
    const float* edge     = (const float*)d_in[1];
    const float* h2       = (const float*)d_in[2];
    const float* angle    = (const float*)d_in[3];
    const float* sw       = (const float*)d_in[4];
    const float* a_sw     = (const float*)d_in[5];
    const float* W_self   = (const float*)d_in[6];
    const float* b_self   = (const float*)d_in[7];
    const float* W_sym    = (const float*)d_in[8];
    const float* b_sym    = (const float*)d_in[9];
    const float* W_ne     = (const float*)d_in[10];
    const float* b_ne     = (const float*)d_in[11];
    const float* W_es     = (const float*)d_in[12];
    const float* b_es     = (const float*)d_in[13];
    const float* W_ea1    = (const float*)d_in[14];
    const float* b_ea1    = (const float*)d_in[15];
    const float* W_ea2    = (const float*)d_in[16];
    const float* b_ea2    = (const float*)d_in[17];
    const float* W_as     = (const float*)d_in[18];
    const float* b_as     = (const float*)d_in[19];
    const float* res_n    = (const float*)d_in[20];
    const float* res_e    = (const float*)d_in[21];
    const float* res_a    = (const float*)d_in[22];
    const int*   nlist    = (const int*)d_in[23];
    // d_in[24], d_in[25]: nlist_mask / a_nlist_mask — all True in this problem's setup

    float* out_node  = (float*)d_out;
    float* out_edge  = out_node + NLOC * NDIM;
    float* out_angle = out_edge + NLOC * NNEI * EDIM;

    if (g_hx.ok) {
        cudaStream_t s0 = 0, s1 = g_hx.s1;
        // chain 0: nodeproj -> edge -> node_fin
        k_nodeproj<<<dim3(NLOC / 16, 5), 128, 0, s0>>>(node_ext, W_self, b_self, W_ne, b_ne,
                                                       W_es, b_es, W_ea1, b_ea1, W_as, b_as);
        cudaEventRecord(g_hx.evNP, s0);
        // chain 1: eproj (independent), then angle after nodeproj
        k_eproj<<<NLOC / 2, 256, 0, s1>>>(edge, W_ea1, W_as);
        cudaStreamWaitEvent(s1, g_hx.evNP, 0);
        k_edge<<<NLOC, 192, 0, s0>>>(node_ext, edge, h2, sw, nlist, W_ne, W_es, res_e, out_edge);
        cudaEventRecord(g_hx.evEdge, s0);
        k_angle<<<NLOC * 2, 64, 0, s1>>>(angle, a_sw, W_ea1, W_as, res_a, out_angle);
        k_node_fin<<<NLOC / 4, 512, 0, s0>>>(node_ext, W_sym, b_sym, res_n, out_node);
        cudaStreamWaitEvent(s1, g_hx.evEdge, 0);
        k_eamsg<<<NLOC / 2, 128, 0, s1>>>(W_ea2, b_ea2, res_e, out_edge);
        cudaEventRecord(g_hx.evJoin, s1);
        cudaStreamWaitEvent(s0, g_hx.evJoin, 0);
    } else {
        // serial fallback (correct, no overlap)
        k_nodeproj<<<dim3(NLOC / 16, 5), 128>>>(node_ext, W_self, b_self, W_ne, b_ne,
                                                W_es, b_es, W_ea1, b_ea1, W_as, b_as);
        k_eproj<<<NLOC / 2, 256>>>(edge, W_ea1, W_as);
        k_edge<<<NLOC, 192>>>(node_ext, edge, h2, sw, nlist, W_ne, W_es, res_e, out_edge);
        k_node_fin<<<NLOC / 4, 512>>>(node_ext, W_sym, b_sym, res_n, out_node);
        k_angle<<<NLOC * 2, 64>>>(angle, a_sw, W_ea1, W_as, res_a, out_angle);
        k_eamsg<<<NLOC / 2, 128>>>(W_ea2, b_ea2, res_e, out_edge);
    }
}

// round 10
// speedup vs baseline: 2.3023x; 1.0256x over previous
#include <cuda_runtime.h>

#define NLOC 1024
#define NNEI 64
#define NDIM 128
#define EDIM 64
#define ADIM 64
#define ASEL 20

typedef unsigned long long ull;

// ---------------- scratch (static device memory; no allocation) ----------------
__device__ float g_pself[NLOC * NDIM];        // silu(node @ W_self + b_self)
__device__ float g_pW0[NLOC * NDIM];          // node @ W0 + b_ne
__device__ float g_pW1[NLOC * NDIM];          // node @ W1
__device__ float g_pV0[NLOC * EDIM];          // node @ V0 + b_es
__device__ float g_pV1[NLOC * EDIM];          // node @ V1
__device__ float g_pA1[NLOC * EDIM];          // node @ A1 + b_ea1
__device__ float g_pB1[NLOC * ADIM];          // node @ B1 + b_as
__device__ float g_eproj[NLOC * ASEL * 4 * 64]; // [l][j][A2,A3,B2,B3][64]
__device__ float g_red[NLOC * ASEL * EDIM];   // reduced angle message
__device__ float g_symin[NLOC * 768];         // grrg concat input to W_sym
__device__ float g_nedge[NLOC * NDIM];        // n_edge

// ---------------- helpers ----------------
__device__ __forceinline__ float silu_f(float x) { return __fdividef(x, 1.0f + __expf(-x)); }

__device__ __forceinline__ ull pack2(float lo, float hi) {
    ull r;
    asm("mov.b64 %0, {%1, %2};" : "=l"(r) : "f"(lo), "f"(hi));
    return r;
}
__device__ __forceinline__ float sum2(ull v) {
    float lo, hi;
    asm("mov.b64 {%0, %1}, %2;" : "=f"(lo), "=f"(hi) : "l"(v));
    return lo + hi;
}
__device__ __forceinline__ void fma2(ull &acc, ull a, ull b) {
    asm("fma.rn.f32x2 %0, %1, %2, %0;" : "+l"(acc) : "l"(a), "l"(b));
}
// 128-bit shared load directly into two 64-bit register pairs (no repacking movs)
__device__ __forceinline__ void lds_2x64(ull &a, ull &b, unsigned saddr) {
    asm volatile("ld.shared.v2.u64 {%0, %1}, [%2];" : "=l"(a), "=l"(b) : "r"(saddr));
}
__device__ __forceinline__ unsigned saddr_of(const void* p) {
    return (unsigned)__cvta_generic_to_shared(p);
}
__device__ __forceinline__ void cp_async16(unsigned sdst, const void* gsrc) {
    asm volatile("cp.async.cg.shared.global [%0], [%1], 16;" :: "r"(sdst), "l"(gsrc));
}
__device__ __forceinline__ void cp_commit() { asm volatile("cp.async.commit_group;"); }
__device__ __forceinline__ void cp_wait0()  { asm volatile("cp.async.wait_group 0;"); }

// ---------------- kernel A: per-node projections (16 nodes / block, pass = blockIdx.y) ----------------
__global__ void __launch_bounds__(128) k_nodeproj(
        const float* __restrict__ node,
        const float* __restrict__ W_self, const float* __restrict__ b_self,
        const float* __restrict__ W_ne,   const float* __restrict__ b_ne,
        const float* __restrict__ W_es,   const float* __restrict__ b_es,
        const float* __restrict__ W_ea1,  const float* __restrict__ b_ea1,
        const float* __restrict__ W_as,   const float* __restrict__ b_as)
{
    const int t    = threadIdx.x;      // 0..127
    const int l0   = blockIdx.x * 16;
    const int pass = blockIdx.y;       // 0:W_self 1:W0 2:W1 3:V0/V1 4:A1/B1
    __shared__ __align__(16) float xs[16][NDIM];
    {
        const float4* src = (const float4*)(node + l0 * NDIM);
        float4* dst = (float4*)(&xs[0][0]);
        #pragma unroll
        for (int i = 0; i < 4; i++) dst[t + 128 * i] = src[t + 128 * i];
    }
    __syncthreads();

    float acc[16];
    #pragma unroll
    for (int m = 0; m < 16; m++) acc[m] = 0.f;

    if (pass < 3) {
        const float* W = (pass == 0) ? W_self : ((pass == 1) ? W_ne : (W_ne + NDIM * NDIM));
        for (int k = 0; k < NDIM; k += 4) {
            float w0 = W[(k + 0) * NDIM + t];
            float w1 = W[(k + 1) * NDIM + t];
            float w2 = W[(k + 2) * NDIM + t];
            float w3 = W[(k + 3) * NDIM + t];
            #pragma unroll
            for (int m = 0; m < 16; m++) {
                float4 x = *(const float4*)(&xs[m][k]);
                acc[m] = fmaf(x.x, w0, acc[m]);
                acc[m] = fmaf(x.y, w1, acc[m]);
                acc[m] = fmaf(x.z, w2, acc[m]);
                acc[m] = fmaf(x.w, w3, acc[m]);
            }
        }
        if (pass == 0) {
            float b = b_self[t];
            #pragma unroll
            for (int m = 0; m < 16; m++) g_pself[(l0 + m) * NDIM + t] = silu_f(acc[m] + b);
        } else if (pass == 1) {
            float b = b_ne[t];
            #pragma unroll
            for (int m = 0; m < 16; m++) g_pW0[(l0 + m) * NDIM + t] = acc[m] + b;
        } else {
            #pragma unroll
            for (int m = 0; m < 16; m++) g_pW1[(l0 + m) * NDIM + t] = acc[m];
        }
    } else {
        const int d = t & 63;
        const float* W;
        if (pass == 3) W = W_es + ((t < 64) ? 0 : NDIM * EDIM) + d;
        else           W = ((t < 64) ? W_ea1 : W_as) + 64 * 64 + d;
        for (int k = 0; k < NDIM; k += 4) {
            float w0 = W[(k + 0) * 64];
            float w1 = W[(k + 1) * 64];
            float w2 = W[(k + 2) * 64];
            float w3 = W[(k + 3) * 64];
            #pragma unroll
            for (int m = 0; m < 16; m++) {
                float4 x = *(const float4*)(&xs[m][k]);
                acc[m] = fmaf(x.x, w0, acc[m]);
                acc[m] = fmaf(x.y, w1, acc[m]);
                acc[m] = fmaf(x.z, w2, acc[m]);
                acc[m] = fmaf(x.w, w3, acc[m]);
            }
        }
        if (pass == 3) {
            if (t < 64) {
                float b = b_es[d];
                #pragma unroll
                for (int m = 0; m < 16; m++) g_pV0[(l0 + m) * EDIM + d] = acc[m] + b;
            } else {
                #pragma unroll
                for (int m = 0; m < 16; m++) g_pV1[(l0 + m) * EDIM + d] = acc[m];
            }
        } else {
            if (t < 64) {
                float b = b_ea1[d];
                #pragma unroll
                for (int m = 0; m < 16; m++) g_pA1[(l0 + m) * EDIM + d] = acc[m] + b;
            } else {
                float b = b_as[d];
                #pragma unroll
                for (int m = 0; m < 16; m++) g_pB1[(l0 + m) * ADIM + d] = acc[m] + b;
            }
        }
    }
}

// ---------------- kernel A2: e_ang projections (A2,A3,B2,B3); 1 node / block ----------------
__global__ void __launch_bounds__(256) k_eproj(const float* __restrict__ edge,
                                               const float* __restrict__ W_ea1,
                                               const float* __restrict__ W_as)
{
    const int t  = threadIdx.x;      // 0..255
    const int l  = blockIdx.x;
    const int which = t >> 6;        // 0:A2 1:A3 2:B2 3:B3
    const int d = t & 63;
    const float* Wsrc = ((which < 2) ? W_ea1 : W_as) + ((which & 1) ? 256 * 64 : 192 * 64) + d;
    ull w2[32];
    #pragma unroll
    for (int kk = 0; kk < 32; kk++)
        w2[kk] = pack2(Wsrc[(2 * kk) * 64], Wsrc[(2 * kk + 1) * 64]);

    __shared__ __align__(16) float rows[ASEL][64];   // 5 KB
    const unsigned rbase = saddr_of(&rows[0][0]);

    {
        const float4* src = (const float4*)(edge + (size_t)l * NNEI * EDIM);
        float4* dst = (float4*)(&rows[0][0]);
        for (int q = t; q < ASEL * 16; q += 256) dst[q] = src[q];
    }
    __syncthreads();
    for (int j = 0; j < ASEL; j += 2) {
        const unsigned a_j0 = rbase + j * 256;
        const unsigned a_j1 = a_j0 + 256;
        ull a0 = 0, a1 = 0, c0 = 0, c1 = 0;
        #pragma unroll
        for (int kk = 0; kk < 16; kk++) {
            ull x0, x1, y0, y1;
            lds_2x64(x0, x1, a_j0 + kk * 16);
            lds_2x64(y0, y1, a_j1 + kk * 16);
            fma2(a0, w2[2 * kk],     x0);
            fma2(a1, w2[2 * kk + 1], x1);
            fma2(c0, w2[2 * kk],     y0);
            fma2(c1, w2[2 * kk + 1], y1);
        }
        g_eproj[((l * ASEL + j)     * 4 + which) * 64 + d] = sum2(a0) + sum2(a1);
        g_eproj[((l * ASEL + j + 1) * 4 + which) * 64 + d] = sum2(c0) + sum2(c1);
    }
}

// ---------------- kernel B: edge path + grrg + n_edge (block per node l) ----------------
__global__ void __launch_bounds__(192) k_edge(const float* __restrict__ node_ext,
                                              const float* __restrict__ edge,
                                              const float* __restrict__ h2,
                                              const float* __restrict__ sw,
                                              const int*   __restrict__ nlist,
                                              const float* __restrict__ W_ne,
                                              const float* __restrict__ W_es,
                                              const float* __restrict__ res_e,
                                              float* __restrict__ out_edge)
{
    const int t = threadIdx.x;   // 0..191
    const int l = blockIdx.x;
    __shared__ __align__(16) float e_sm[NNEI][EDIM];  // 16 KB
    __shared__ float sw_sm[NNEI];
    __shared__ int   nl_sm[NNEI];
    __shared__ float h2_sm[NNEI][3];
    __shared__ float hg_sm[3 * NDIM + 3 * EDIM];

    {
        const float4* src = (const float4*)(edge + (size_t)l * NNEI * EDIM);
        float4* dst = (float4*)(&e_sm[0][0]);
        for (int i = t; i < NNEI * EDIM / 4; i += 192) dst[i] = src[i];
        for (int i = t; i < NNEI; i += 192) { sw_sm[i] = sw[l * NNEI + i]; nl_sm[i] = nlist[l * NNEI + i]; }
        for (int i = t; i < NNEI * 3; i += 192) h2_sm[i / 3][i % 3] = h2[l * NNEI * 3 + i];
    }
    __syncthreads();

    const bool isA = (t < NDIM);
    const int  d   = t - NDIM;   // only meaningful for !isA
    ull w2[32];
    if (isA) {
        #pragma unroll
        for (int kk = 0; kk < 32; kk++)
            w2[kk] = pack2(W_ne[(256 + 2 * kk) * NDIM + t], W_ne[(256 + 2 * kk + 1) * NDIM + t]);
    } else {
        #pragma unroll
        for (int kk = 0; kk < 32; kk++)
            w2[kk] = pack2(W_es[(256 + 2 * kk) * EDIM + d], W_es[(256 + 2 * kk + 1) * EDIM + d]);
    }
    const float pv0 = isA ? g_pW0[l * NDIM + t] : g_pV0[l * EDIM + d];
    const float rese0 = isA ? 0.f : res_e[d];
    const unsigned ebase = saddr_of(&e_sm[0][0]);

    float accNE = 0.f, hg0 = 0.f, hg1 = 0.f, hg2 = 0.f;

    for (int n = 0; n < NNEI; n += 2) {
        const int   idx0 = nl_sm[n],     idx1 = nl_sm[n + 1];
        const float sw0  = sw_sm[n],     sw1  = sw_sm[n + 1];
        // hoist random gathers so they overlap the fma chains
        float gproj0, gproj1, gnode0 = 0.f, gnode1 = 0.f;
        if (isA) {
            gproj0 = g_pW1[idx0 * NDIM + t];
            gproj1 = g_pW1[idx1 * NDIM + t];
            gnode0 = node_ext[idx0 * NDIM + t];
            gnode1 = node_ext[idx1 * NDIM + t];
        } else {
            gproj0 = g_pV1[idx0 * EDIM + d];
            gproj1 = g_pV1[idx1 * EDIM + d];
        }
        const unsigned a_n0 = ebase + n * 256;
        const unsigned a_n1 = a_n0 + 256;
        ull a0 = 0, a1 = 0, c0 = 0, c1 = 0;
        #pragma unroll
        for (int kk = 0; kk < 16; kk++) {
            ull x0, x1, y0, y1;
            lds_2x64(x0, x1, a_n0 + kk * 16);
            lds_2x64(y0, y1, a_n1 + kk * 16);
            fma2(a0, w2[2 * kk],     x0);
            fma2(a1, w2[2 * kk + 1], x1);
            fma2(c0, w2[2 * kk],     y0);
            fma2(c1, w2[2 * kk + 1], y1);
        }
        float s0 = sum2(a0) + sum2(a1) + pv0 + gproj0;
        float s1 = sum2(c0) + sum2(c1) + pv0 + gproj1;
        if (isA) {
            accNE = fmaf(silu_f(s0), sw0, accNE);
            accNE = fmaf(silu_f(s1), sw1, accNE);
            float gw0 = gnode0 * sw0;
            float gw1 = gnode1 * sw1;
            hg0 = fmaf(h2_sm[n][0], gw0, fmaf(h2_sm[n + 1][0], gw1, hg0));
            hg1 = fmaf(h2_sm[n][1], gw0, fmaf(h2_sm[n + 1][1], gw1, hg1));
            hg2 = fmaf(h2_sm[n][2], gw0, fmaf(h2_sm[n + 1][2], gw1, hg2));
        } else {
            float ev0 = e_sm[n][d], ev1 = e_sm[n + 1][d];
            out_edge[(l * NNEI + n)     * EDIM + d] = fmaf(rese0, silu_f(s0), ev0);
            out_edge[(l * NNEI + n + 1) * EDIM + d] = fmaf(rese0, silu_f(s1), ev1);
            float ge0 = ev0 * sw0, ge1 = ev1 * sw1;
            hg0 = fmaf(h2_sm[n][0], ge0, fmaf(h2_sm[n + 1][0], ge1, hg0));
            hg1 = fmaf(h2_sm[n][1], ge0, fmaf(h2_sm[n + 1][1], ge1, hg1));
            hg2 = fmaf(h2_sm[n][2], ge0, fmaf(h2_sm[n + 1][2], ge1, hg2));
        }
    }
    const float inv_nnei = 1.0f / NNEI;
    if (isA) {
        g_nedge[l * NDIM + t] = accNE * inv_nnei;
        hg_sm[0 * NDIM + t] = hg0 * inv_nnei;
        hg_sm[1 * NDIM + t] = hg1 * inv_nnei;
        hg_sm[2 * NDIM + t] = hg2 * inv_nnei;
    } else {
        hg_sm[3 * NDIM + 0 * EDIM + d] = hg0 * inv_nnei;
        hg_sm[3 * NDIM + 1 * EDIM + d] = hg1 * inv_nnei;
        hg_sm[3 * NDIM + 2 * EDIM + d] = hg2 * inv_nnei;
    }
    __syncthreads();

    // grrg outer products -> g_symin[l][768]   ([grrg(edge) 256 | grrg(nei) 512])
    const float third = 1.0f / 3.0f;
    #pragma unroll
    for (int g = 0; g < 4; g++) {
        int v = t + g * 192;
        float o;
        if (v < 256) {
            int a = v >> 6, dd = v & 63;
            const float* he = hg_sm + 3 * NDIM;
            o = (he[0 * EDIM + a] * he[0 * EDIM + dd] +
                 he[1 * EDIM + a] * he[1 * EDIM + dd] +
                 he[2 * EDIM + a] * he[2 * EDIM + dd]) * third;
        } else {
            int vv = v - 256;
            int a = vv >> 7, c = vv & 127;
            o = (hg_sm[0 * NDIM + a] * hg_sm[0 * NDIM + c] +
                 hg_sm[1 * NDIM + a] * hg_sm[1 * NDIM + c] +
                 hg_sm[2 * NDIM + a] * hg_sm[2 * NDIM + c]) * third;
        }
        g_symin[l * 768 + v] = o;
    }
}

// ---------------- kernel E: node_sym GEMM + finalize (4 nodes / block, split-k 4, 512 thr) ----------------
__global__ void __launch_bounds__(512) k_node_fin(const float* __restrict__ node,
                                                  const float* __restrict__ W_sym,
                                                  const float* __restrict__ b_sym,
                                                  const float* __restrict__ res_n,
                                                  float* __restrict__ out_node)
{
    const int t  = threadIdx.x;     // 0..511
    const int tt = t & 127;
    const int q  = t >> 7;          // k quarter 0..3
    const int l0 = blockIdx.x * 4;
    __shared__ __align__(16) float xs[4][768];   // 12 KB
    __shared__ float part[3][4][NDIM];           // 6 KB
    {
        const float4* src = (const float4*)(g_symin + (size_t)l0 * 768);
        float4* dst = (float4*)(&xs[0][0]);
        for (int i = t; i < 768; i += 512) dst[i] = src[i];
    }
    __syncthreads();

    float acc[4] = {0.f, 0.f, 0.f, 0.f};
    const int k0 = q * 192;
    #pragma unroll 2
    for (int k = k0; k < k0 + 192; k += 4) {
        float w0 = W_sym[(k + 0) * NDIM + tt];
        float w1 = W_sym[(k + 1) * NDIM + tt];
        float w2 = W_sym[(k + 2) * NDIM + tt];
        float w3 = W_sym[(k + 3) * NDIM + tt];
        #pragma unroll
        for (int m = 0; m < 4; m++) {
            float4 x = *(const float4*)(&xs[m][k]);
            acc[m] = fmaf(x.x, w0, acc[m]);
            acc[m] = fmaf(x.y, w1, acc[m]);
            acc[m] = fmaf(x.z, w2, acc[m]);
            acc[m] = fmaf(x.w, w3, acc[m]);
        }
    }
    if (q > 0) {
        #pragma unroll
        for (int m = 0; m < 4; m++) part[q - 1][m][tt] = acc[m];
    }
    __syncthreads();
    if (q == 0) {
        const float b  = b_sym[tt];
        const float r0 = res_n[tt], r1 = res_n[NDIM + tt], r2 = res_n[2 * NDIM + tt];
        #pragma unroll
        for (int m = 0; m < 4; m++) {
            const int l = l0 + m;
            float s = acc[m] + part[0][m][tt] + part[1][m][tt] + part[2][m][tt] + b;
            float ns = silu_f(s);
            out_node[l * NDIM + tt] = node[l * NDIM + tt]
                                    + r0 * g_pself[l * NDIM + tt]
                                    + r1 * ns
                                    + r2 * g_nedge[l * NDIM + tt];
        }
    }
}

// ---------------- kernel C: fused angle path, A+B per thread, cp.async pipeline ----------------
// 4 blocks per node (5 i's each), 64 threads.
__global__ void __launch_bounds__(64) k_angle(const float* __restrict__ angle,
                                              const float* __restrict__ a_sw,
                                              const float* __restrict__ W_ea1,
                                              const float* __restrict__ W_as,
                                              const float* __restrict__ res_a,
                                              float* __restrict__ out_angle)
{
    const int d  = threadIdx.x;          // 0..63 — output channel, both paths
    const int l  = blockIdx.x >> 2;
    const int i0 = (blockIdx.x & 3) * 5;
    const int NI = 5;

    // both weight matrices resident: A0 (W_ea1 rows 0..63) and B0 (W_as rows 0..63)
    ull wA[32], wB[32];
    #pragma unroll
    for (int kk = 0; kk < 32; kk++) {
        wA[kk] = pack2(W_ea1[(2 * kk) * 64 + d], W_ea1[(2 * kk + 1) * 64 + d]);
        wB[kk] = pack2(W_as [(2 * kk) * 64 + d], W_as [(2 * kk + 1) * 64 + d]);
    }

    __shared__ __align__(16) float rows[2][ASEL][64];   // 10 KB double buffer
    __shared__ __align__(16) float a2s[ASEL][64];       // A2[e_ang[l,j]] adds (5 KB)
    __shared__ __align__(16) float b2s[ASEL][64];       // B2[e_ang[l,j]] adds (5 KB)
    __shared__ float asw_sm[ASEL];

    const float* eproj_l = g_eproj + (size_t)l * ASEL * 256;

    // kick off async copy of the first tile before doing setup work
    {
        const float* src = angle + (size_t)((l * ASEL + i0) * ASEL) * 64;
        unsigned sdst = saddr_of(&rows[0][0][0]);
        #pragma unroll
        for (int r = 0; r < 5; r++)
            cp_async16(sdst + (d + 64 * r) * 16, src + (d + 64 * r) * 4);
        cp_commit();
    }

    if (d < ASEL) asw_sm[d] = a_sw[l * ASEL + d];
    {
        float4* a4 = (float4*)(&a2s[0][0]);
        float4* b4 = (float4*)(&b2s[0][0]);
        #pragma unroll
        for (int r = 0; r < 5; r++) {
            int idx = d + 64 * r;           // 0..319
            int j = idx >> 4, q = idx & 15;
            a4[idx] = ((const float4*)(eproj_l + j * 256 +   0))[q];
            b4[idx] = ((const float4*)(eproj_l + j * 256 + 128))[q];
        }
    }
    const float cA1  = g_pA1[l * 64 + d];
    const float cB1  = g_pB1[l * 64 + d];
    const float resv = res_a[d];
    const float inv_sqrt_asel = 0.22360679774997896f;   // 1/sqrt(20)

    int buf = 0;
    for (int ii = 0; ii < NI; ii++) {
        const int i = i0 + ii;
        cp_wait0();          // this thread's slices of tile ii landed
        __syncthreads();     // all threads' slices visible; prev compute on buf^1 done

        // prefetch tile ii+1 into the other buffer (fully hidden behind compute)
        if (ii + 1 < NI) {
            const float* src = angle + (size_t)((l * ASEL + i + 1) * ASEL) * 64;
            unsigned sdst = saddr_of(&rows[buf ^ 1][0][0]);
            #pragma unroll
            for (int r = 0; r < 5; r++)
                cp_async16(sdst + (d + 64 * r) * 16, src + (d + 64 * r) * 4);
            cp_commit();
        }

        const float baseA = cA1 + eproj_l[i * 256 +  64 + d];   // + A3[e_ang[l,i]]
        const float baseB = cB1 + eproj_l[i * 256 + 192 + d];   // + B3[e_ang[l,i]]
        float red = 0.f;
        const unsigned rb = saddr_of(&rows[buf][0][0]);
        #pragma unroll 2
        for (int j = 0; j < ASEL; j += 2) {
            const unsigned aj0 = rb + j * 256;
            const unsigned aj1 = aj0 + 256;
            ull A00 = 0, A01 = 0, B00 = 0, B01 = 0;
            ull A10 = 0, A11 = 0, B10 = 0, B11 = 0;
            #pragma unroll
            for (int kk = 0; kk < 16; kk++) {
                ull x0, x1, y0, y1;
                lds_2x64(x0, x1, aj0 + kk * 16);
                lds_2x64(y0, y1, aj1 + kk * 16);
                fma2(A00, wA[2 * kk],     x0);
                fma2(A01, wA[2 * kk + 1], x1);
                fma2(B00, wB[2 * kk],     x0);
                fma2(B01, wB[2 * kk + 1], x1);
                fma2(A10, wA[2 * kk],     y0);
                fma2(A11, wA[2 * kk + 1], y1);
                fma2(B10, wB[2 * kk],     y0);
                fma2(B11, wB[2 * kk + 1], y1);
            }
            const float vA0 = silu_f(sum2(A00) + sum2(A01) + baseA + a2s[j][d]);
            const float vB0 = silu_f(sum2(B00) + sum2(B01) + baseB + b2s[j][d]);
            const float vA1 = silu_f(sum2(A10) + sum2(A11) + baseA + a2s[j + 1][d]);
            const float vB1 = silu_f(sum2(B10) + sum2(B11) + baseB + b2s[j + 1][d]);
            red = fmaf(asw_sm[j],     vA0, red);
            red = fmaf(asw_sm[j + 1], vA1, red);
            const size_t o = (size_t)((l * ASEL + i) * ASEL + j) * 64 + d;
            out_angle[o]      = fmaf(resv, vB0, rows[buf][j][d]);
            out_angle[o + 64] = fmaf(resv, vB1, rows[buf][j + 1][d]);
        }
        g_red[(l * ASEL + i) * 64 + d] = red * asw_sm[i] * inv_sqrt_asel;
        buf ^= 1;
    }
}

// ---------------- kernel D: e_angle_msg GEMM + edge finalize (2 nodes / block) ----------------
__global__ void __launch_bounds__(128) k_eamsg(const float* __restrict__ W_ea2,
                                               const float* __restrict__ b_ea2,
                                               const float* __restrict__ res_e,
                                               float* __restrict__ out_edge)
{
    const int t = threadIdx.x;   // 0..127
    const int d = t & 63;
    const int l = blockIdx.x * 2 + (t >> 6);
    ull w2[32];
    #pragma unroll
    for (int kk = 0; kk < 32; kk++)
        w2[kk] = pack2(W_ea2[(2 * kk) * 64 + d], W_ea2[(2 * kk + 1) * 64 + d]);
    const float b   = b_ea2[d];
    const float re1 = res_e[64 + d];

    __shared__ __align__(16) float xs[2][ASEL][64];   // 10 KB
    {
        const float4* src = (const float4*)(g_red + (size_t)(blockIdx.x * 2) * ASEL * 64);
        float4* dst = (float4*)(&xs[0][0][0]);
        for (int q = t; q < 2 * ASEL * 16; q += 128) dst[q] = src[q];
    }
    __syncthreads();

    const unsigned xbase = saddr_of(&xs[t >> 6][0][0]);
    const float ypad = re1 * silu_f(b);   // padded rows contribute silu(b)
    for (int i = 0; i < NNEI; i++) {
        float add;
        if (i < ASEL) {
            const unsigned a_i = xbase + i * 256;
            ull a0 = 0, a1 = 0;
            #pragma unroll
            for (int kk = 0; kk < 16; kk++) {
                ull x0, x1;
                lds_2x64(x0, x1, a_i + kk * 16);
                fma2(a0, w2[2 * kk],     x0);
                fma2(a1, w2[2 * kk + 1], x1);
            }
            add = re1 * silu_f(sum2(a0) + sum2(a1) + b);
        } else {
            add = ypad;
        }
        const size_t o = (size_t)(l * NNEI + i) * 64 + d;
        out_edge[o] += add;
    }
}

// ---------------- stream/event resources (created once, at load time) ----------------
struct HxStreams {
    cudaStream_t s1 = nullptr;
    cudaEvent_t  evNP = nullptr, evEdge = nullptr, evJoin = nullptr;
    bool ok = false;
    HxStreams() {
        ok = (cudaStreamCreateWithFlags(&s1, cudaStreamNonBlocking) == cudaSuccess) &&
             (cudaEventCreateWithFlags(&evNP,   cudaEventDisableTiming) == cudaSuccess) &&
             (cudaEventCreateWithFlags(&evEdge, cudaEventDisableTiming) == cudaSuccess) &&
             (cudaEventCreateWithFlags(&evJoin, cudaEventDisableTiming) == cudaSuccess);
    }
};
static HxStreams g_hx;

// ---------------- launch ----------------
extern "C" void kernel_launch(void* const* d_in, const int* in_sizes, int n_in,
                              void* d_out, int out_size)
{
    (void)in_sizes; (void)n_in; (void)out_size;
    const float* node_ext = (const float*)d_in[0];
    const float* edge     = (const float*)d_in[1];
    const float* h2       = (const float*)d_in[2];
    const float* angle    = (const float*)d_in[3];
    const float* sw       = (const float*)d_in[4];
    const float* a_sw     = (const float*)d_in[5];
    const float* W_self   = (const float*)d_in[6];
    const float* b_self   = (const float*)d_in[7];
    const float* W_sym    = (const float*)d_in[8];
    const float* b_sym    = (const float*)d_in[9];
    const float* W_ne     = (const float*)d_in[10];
    const float* b_ne     = (const float*)d_in[11];
    const float* W_es     = (const float*)d_in[12];
    const float* b_es     = (const float*)d_in[13];
    const float* W_ea1    = (const float*)d_in[14];
    const float* b_ea1    = (const float*)d_in[15];
    const float* W_ea2    = (const float*)d_in[16];
    const float* b_ea2    = (const float*)d_in[17];
    const float* W_as     = (const float*)d_in[18];
    const float* b_as     = (const float*)d_in[19];
    const float* res_n    = (const float*)d_in[20];
    const float* res_e    = (const float*)d_in[21];
    const float* res_a    = (const float*)d_in[22];
    const int*   nlist    = (const int*)d_in[23];
    // d_in[24], d_in[25]: nlist_mask / a_nlist_mask — all True in this problem's setup

    float* out_node  = (float*)d_out;
    float* out_edge  = out_node + NLOC * NDIM;
    float* out_angle = out_edge + NLOC * NNEI * EDIM;

    if (g_hx.ok) {
        cudaStream_t s0 = 0, s1 = g_hx.s1;
        // chain 0: nodeproj -> edge -> node_fin
        k_nodeproj<<<dim3(NLOC / 16, 5), 128, 0, s0>>>(node_ext, W_self, b_self, W_ne, b_ne,
                                                       W_es, b_es, W_ea1, b_ea1, W_as, b_as);
        cudaEventRecord(g_hx.evNP, s0);
        // chain 1: eproj (independent), then angle after nodeproj
        k_eproj<<<NLOC, 256, 0, s1>>>(edge, W_ea1, W_as);
        cudaStreamWaitEvent(s1, g_hx.evNP, 0);
        k_edge<<<NLOC, 192, 0, s0>>>(node_ext, edge, h2, sw, nlist, W_ne, W_es, res_e, out_edge);
        cudaEventRecord(g_hx.evEdge, s0);
        k_angle<<<NLOC * 4, 64, 0, s1>>>(angle, a_sw, W_ea1, W_as, res_a, out_angle);
        k_node_fin<<<NLOC / 4, 512, 0, s0>>>(node_ext, W_sym, b_sym, res_n, out_node);
        cudaStreamWaitEvent(s1, g_hx.evEdge, 0);
        k_eamsg<<<NLOC / 2, 128, 0, s1>>>(W_ea2, b_ea2, res_e, out_edge);
        cudaEventRecord(g_hx.evJoin, s1);
        cudaStreamWaitEvent(s0, g_hx.evJoin, 0);
    } else {
        // serial fallback (correct, no overlap)
        k_nodeproj<<<dim3(NLOC / 16, 5), 128>>>(node_ext, W_self, b_self, W_ne, b_ne,
                                                W_es, b_es, W_ea1, b_ea1, W_as, b_as);
        k_eproj<<<NLOC, 256>>>(edge, W_ea1, W_as);
        k_edge<<<NLOC, 192>>>(node_ext, edge, h2, sw, nlist, W_ne, W_es, res_e, out_edge);
        k_node_fin<<<NLOC / 4, 512>>>(node_ext, W_sym, b_sym, res_n, out_node);
        k_angle<<<NLOC * 4, 64>>>(angle, a_sw, W_ea1, W_as, res_a, out_angle);
        k_eamsg<<<NLOC / 2, 128>>>(W_ea2, b_ea2, res_e, out_edge);
    }
}